// round 7
// baseline (speedup 1.0000x reference)
#include <cuda_runtime.h>
#include <cuda_bf16.h>
#include <math.h>
#include <stdint.h>

#define BB 256
#define TT 128
#define DD 64
#define HH 512
#define AA 128
#define OO 32
#define NCAT 1536
#define NBLK 128
#define NTHR 512

// ---------------- device scratch ----------------
__device__ float g_K[BB * TT * AA];
__device__ float g_V[BB * TT * AA];
__device__ uint32_t g_WBHi[NCAT * 256];   // W^T bf16x2 pairs along k: [n][kpair]
__device__ uint32_t g_WBLo[NCAT * 256];
__device__ float g_ctx[BB * AA];
__device__ float g_h[BB * HH];
__device__ float g_dA[BB * HH];           // delta buffers (h_s - h)
__device__ float g_dB[BB * HH];
__device__ float g_k1[BB * HH];
__device__ float g_k2[BB * HH];
__device__ float g_k3[BB * HH];
__device__ float g_leak[HH];
__device__ unsigned g_cnt[9];
__device__ volatile unsigned g_gen[9];

__device__ __forceinline__ float softplusf(float x) {
    return (x > 20.f) ? x : log1pf(expf(x));
}
__device__ __forceinline__ float sigmoidf(float x) {
    return 1.f / (1.f + expf(-x));
}
__device__ __forceinline__ void mma16(float* d, const uint32_t* a, const uint32_t* b) {
    asm volatile(
        "mma.sync.aligned.m16n8k16.row.col.f32.bf16.bf16.f32 "
        "{%0,%1,%2,%3},{%4,%5,%6,%7},{%8,%9},{%0,%1,%2,%3};"
        : "+f"(d[0]), "+f"(d[1]), "+f"(d[2]), "+f"(d[3])
        : "r"(a[0]), "r"(a[1]), "r"(a[2]), "r"(a[3]), "r"(b[0]), "r"(b[1]));
}
__device__ __forceinline__ uint32_t pack_bf2(float a, float b) {
    __nv_bfloat162 t = __floats2bfloat162_rn(a, b);
    return *(uint32_t*)&t;
}

// ---------------- barrier ----------------
__device__ __forceinline__ void gbar(int idx, unsigned nArr) {
    __threadfence();
    __syncthreads();
    if (threadIdx.x == 0) {
        unsigned gen = g_gen[idx];
        if (atomicAdd(&g_cnt[idx], 1u) == nArr - 1) {
            g_cnt[idx] = 0;
            __threadfence();
            g_gen[idx] = gen + 1;
        } else {
            while (g_gen[idx] == gen) __nanosleep(32);
        }
        __threadfence();
    }
    __syncthreads();
}

// smem layout:
//  [0, 8192):      sbase[32][64]        (persists across step's 4 stages)
//  [8192, 20480):  sz0[32][96]          (persists across step's 4 stages)
//  [20480, ...):   union:
//    stage: AsHi[64][17]u32 | AsLo[64][17] | BsHi[192][17] | BsLo[192][17] | zz[64][96]f
//           (zz also aliased as cz[32][192] for base staging)
//    kv:    hrow[32][516]f  (66048 B)
//    attn:  small scratch
#define OFF_UN    20480
#define OFF_ASHI  (OFF_UN)
#define OFF_ASLO  (OFF_UN + 4352)
#define OFF_BSHI  (OFF_UN + 8704)
#define OFF_BSLO  (OFF_UN + 21760)
#define OFF_Z     (OFF_UN + 34816)
#define SMEM_BYTES (20480 + 66048)

typedef uint32_t U17[17];

// ---------------- megakernel ----------------
__global__ void __launch_bounds__(NTHR, 1) mega(
    const float* __restrict__ x_states, const float* __restrict__ x_dts,
    const float* __restrict__ Wq, const float* __restrict__ bq,
    const float* __restrict__ Wk, const float* __restrict__ bk,
    const float* __restrict__ Wv, const float* __restrict__ bv,
    const float* __restrict__ W_gd, const float* __restrict__ b_gd,
    const float* __restrict__ W_tau, const float* __restrict__ b_tau,
    const float* __restrict__ gleak, const float* __restrict__ cm,
    const float* __restrict__ W_fc, const float* __restrict__ b_fc,
    float* __restrict__ out)
{
    extern __shared__ char smraw[];
    float (*sbase)[64] = (float(*)[64])(smraw);
    float (*sz0)[96]   = (float(*)[96])(smraw + 8192);
    char* un = smraw + OFF_UN;

    int bid = blockIdx.x;
    int tid = threadIdx.x;
    int gtid = bid * NTHR + tid;
    int lane = tid & 31;
    int wid = tid >> 5;
    int gid = bid >> 4;                 // batch group (32 batches)
    int hg  = bid & 15;                 // h-col group (32 h)
    int m0 = gid * 32;
    int h0 = hg * 32;

    // ===== prep =====
    if (gtid < HH) g_leak[gtid] = softplusf(cm[gtid]) + softplusf(gleak[gtid]);
    g_h[gtid] = 0.f;
    g_h[65536 + gtid] = 0.f;
    for (int idx = gtid; idx < NCAT * 256; idx += NBLK * NTHR) {
        int n = idx >> 8, kq = idx & 255;
        int g = n / 96, c = n - g * 96;
        int k0 = kq * 2;
        float w0, w1;
        if (c < 32) {
            w0 = W_gd[(64 + k0) * 1024 + g * 32 + c];
            w1 = W_gd[(64 + k0 + 1) * 1024 + g * 32 + c];
        } else if (c < 64) {
            w0 = W_gd[(64 + k0) * 1024 + 512 + g * 32 + (c - 32)];
            w1 = W_gd[(64 + k0 + 1) * 1024 + 512 + g * 32 + (c - 32)];
        } else {
            w0 = W_tau[k0 * 512 + g * 32 + (c - 64)];
            w1 = W_tau[(k0 + 1) * 512 + g * 32 + (c - 64)];
        }
        float hi0 = __bfloat162float(__float2bfloat16(w0));
        float hi1 = __bfloat162float(__float2bfloat16(w1));
        g_WBHi[idx] = pack_bf2(hi0, hi1);
        g_WBLo[idx] = pack_bf2(w0 - hi0, w1 - hi1);
    }
    gbar(8, NBLK);

    // ===== time loop =====
    for (int t = 0; t < TT; t++) {
        // ---- KV: row t-1 = g_h @ [Wk|Wv]; tile 32b x 16n per block ----
        if (t > 0) {
            float (*hrow)[516] = (float(*)[516])un;
#pragma unroll
            for (int i = 0; i < 8; i++) {
                int idx = i * 512 + tid;            // < 4096 float4
                int rr = idx >> 7, c4 = (idx & 127) << 2;
                float4 v = *(const float4*)&g_h[(m0 + rr) * HH + c4];
                *(float4*)&hrow[rr][c4] = v;
            }
            __syncthreads();
            int tx = tid & 15, ty = tid >> 4;       // ty 0..31 = batch
            int nn = hg * 16 + tx;                   // 0..255
            const float* W = (nn < 128) ? Wk : Wv;
            int ncol = nn & 127;
            float acc = (nn < 128) ? bk[ncol] : bv[ncol];
            const float* hr = hrow[ty];
#pragma unroll 8
            for (int k = 0; k < HH; k++) acc += hr[k] * W[k * AA + ncol];
            float* dst = (nn < 128) ? g_K : g_V;
            dst[((m0 + ty) * TT + (t - 1)) * AA + ncol] = acc;
            gbar(gid, 16);
        }

        // ---- ATTN: 2 batches per block ----
        {
            float* aq   = (float*)un;               // [2][128]
            float* asc  = aq + 256;                 // [2][128]
            float* actx = asc + 256;                // [2][2][128]
            float* axs  = actx + 512;               // [2][64]
            float* ared = axs + 128;                // [2][8]
            int hB = tid >> 8;
            int lt = tid & 255;
            int b = bid * 2 + hB;
            if (t == 0) {
                if (lt < 128) g_ctx[b * AA + lt] = 0.f;
            } else {
                if (lt < DD) axs[hB * 64 + lt] = x_states[(b * TT + t) * DD + lt];
                __syncthreads();
                if (lt < 128) {
                    float qv = bq[lt];
#pragma unroll 16
                    for (int d = 0; d < DD; d++) qv += axs[hB * 64 + d] * Wq[d * AA + lt];
                    aq[hB * 128 + lt] = qv;
                }
                __syncthreads();
                float s = -1e30f;
                if (lt < t) {
                    const float4* Kp = (const float4*)&g_K[(b * TT + lt) * AA];
                    const float* qh = &aq[hB * 128];
                    float dot = 0.f;
#pragma unroll 8
                    for (int a4 = 0; a4 < AA / 4; a4++) {
                        float4 kv = Kp[a4];
                        dot += kv.x * qh[4 * a4] + kv.y * qh[4 * a4 + 1] +
                               kv.z * qh[4 * a4 + 2] + kv.w * qh[4 * a4 + 3];
                    }
                    s = dot * (1.f / 11.313708498984761f);
                }
                float m = s;
#pragma unroll
                for (int o = 16; o > 0; o >>= 1) m = fmaxf(m, __shfl_xor_sync(0xffffffffu, m, o));
                if (lane == 0) ared[hB * 8 + (wid & 7)] = m;
                __syncthreads();
                m = ared[hB * 8];
#pragma unroll
                for (int i = 1; i < 8; i++) m = fmaxf(m, ared[hB * 8 + i]);
                float e = (lt < t) ? expf(s - m) : 0.f;
                float su = e;
#pragma unroll
                for (int o = 16; o > 0; o >>= 1) su += __shfl_xor_sync(0xffffffffu, su, o);
                __syncthreads();
                if (lane == 0) ared[hB * 8 + (wid & 7)] = su;
                __syncthreads();
                su = 0.f;
#pragma unroll
                for (int i = 0; i < 8; i++) su += ared[hB * 8 + i];
                if (lt < 128) asc[hB * 128 + lt] = e / su;
                __syncthreads();
                {
                    int a = lt & 127, th = lt >> 7;
                    float c = 0.f;
                    for (int sx = th; sx < t; sx += 2)
                        c += asc[hB * 128 + sx] * g_V[(b * TT + sx) * AA + a];
                    actx[(hB * 2 + th) * 128 + a] = c;
                }
                __syncthreads();
                if (lt < 128)
                    g_ctx[b * AA + lt] = actx[hB * 256 + lt] + actx[hB * 256 + 128 + lt];
            }
            gbar(gid, 16);
        }

        // ---- 4 RK stages ----
        U17* AsHi = (U17*)(smraw + OFF_ASHI);       // [64] = kh*32 + m
        U17* AsLo = (U17*)(smraw + OFF_ASLO);
        U17* BsHi = (U17*)(smraw + OFF_BSHI);       // [192] = kh*96 + n
        U17* BsLo = (U17*)(smraw + OFF_BSLO);
        float (*zz)[96] = (float(*)[96])(smraw + OFF_Z);   // [64] = kh*32 + m

        for (int stage = 0; stage < 4; stage++) {
            const float* Ag = (stage == 0) ? g_h : ((stage == 2) ? g_dB : g_dA);
            int kh = wid >> 3;
            int wl = wid & 7;
            int wm = (wl >> 2) * 16;
            int wn = (wl & 3) * 24;
            int ltid = tid & 255;
            int lm = ltid >> 3, lk = (ltid & 7) * 4;
            int r = wm + (lane >> 2);
            int qa = lane & 3;
            int kk0 = kh * 256;

            if (stage == 0) {
                // base GEMM into sbase (staging in cz = zz region)
                float (*cz)[192] = (float(*)[192])(smraw + OFF_Z);
#pragma unroll
                for (int i = 0; i < 12; i++) {
                    int idx = i * 512 + tid;        // < 6144
                    int bl = idx / 192, k = idx - bl * 192;
                    cz[bl][k] = (k < 64) ? x_states[((m0 + bl) * TT + t) * DD + k]
                                         : g_ctx[(m0 + bl) * AA + (k - 64)];
                }
                __syncthreads();
                {
                    int tx2 = tid & 63, ty2 = tid >> 6;
                    int col = (tx2 < 32) ? (h0 + tx2) : (512 + h0 + (tx2 - 32));
                    float acc[4] = {0.f, 0.f, 0.f, 0.f};
#pragma unroll 8
                    for (int k = 0; k < 64; k++) {
                        float w = W_gd[k * 1024 + col];
                        acc[0] += cz[ty2 * 4 + 0][k] * w;
                        acc[1] += cz[ty2 * 4 + 1][k] * w;
                        acc[2] += cz[ty2 * 4 + 2][k] * w;
                        acc[3] += cz[ty2 * 4 + 3][k] * w;
                    }
#pragma unroll 8
                    for (int k = 64; k < 192; k++) {
                        float w = W_gd[(k + 512) * 1024 + col];
                        acc[0] += cz[ty2 * 4 + 0][k] * w;
                        acc[1] += cz[ty2 * 4 + 1][k] * w;
                        acc[2] += cz[ty2 * 4 + 2][k] * w;
                        acc[3] += cz[ty2 * 4 + 3][k] * w;
                    }
                    float bg = b_gd[col];
#pragma unroll
                    for (int i2 = 0; i2 < 4; i2++)
                        sbase[ty2 * 4 + i2][tx2] = acc[i2] + bg;
                }
                __syncthreads();

                // 3-term bf16 split GEMM: z0 = h @ Wpack
                float acc[3][4];
#pragma unroll
                for (int s = 0; s < 3; s++)
#pragma unroll
                    for (int i = 0; i < 4; i++) acc[s][i] = 0.f;
                for (int it = 0; it < 8; it++) {
                    int kk = kk0 + it * 32;
                    float4 v = *(const float4*)&Ag[(m0 + lm) * HH + kk + lk];
                    float hx = __bfloat162float(__float2bfloat16(v.x));
                    float hy = __bfloat162float(__float2bfloat16(v.y));
                    float hz = __bfloat162float(__float2bfloat16(v.z));
                    float hw = __bfloat162float(__float2bfloat16(v.w));
                    AsHi[kh * 32 + lm][(lk >> 1) + 0] = pack_bf2(hx, hy);
                    AsHi[kh * 32 + lm][(lk >> 1) + 1] = pack_bf2(hz, hw);
                    AsLo[kh * 32 + lm][(lk >> 1) + 0] = pack_bf2(v.x - hx, v.y - hy);
                    AsLo[kh * 32 + lm][(lk >> 1) + 1] = pack_bf2(v.z - hz, v.w - hw);
#pragma unroll
                    for (int i = 0; i < 6; i++) {
                        int idx = i * 256 + ltid;
                        int n = idx >> 4, kq = idx & 15;
                        BsHi[kh * 96 + n][kq] = g_WBHi[(hg * 96 + n) * 256 + (kk >> 1) + kq];
                        BsLo[kh * 96 + n][kq] = g_WBLo[(hg * 96 + n) * 256 + (kk >> 1) + kq];
                    }
                    __syncthreads();
#pragma unroll
                    for (int kb2 = 0; kb2 < 16; kb2 += 8) {
                        uint32_t ahi[4], alo[4];
                        ahi[0] = AsHi[kh * 32 + r][kb2 + qa];
                        ahi[1] = AsHi[kh * 32 + r + 8][kb2 + qa];
                        ahi[2] = AsHi[kh * 32 + r][kb2 + 4 + qa];
                        ahi[3] = AsHi[kh * 32 + r + 8][kb2 + 4 + qa];
                        alo[0] = AsLo[kh * 32 + r][kb2 + qa];
                        alo[1] = AsLo[kh * 32 + r + 8][kb2 + qa];
                        alo[2] = AsLo[kh * 32 + r][kb2 + 4 + qa];
                        alo[3] = AsLo[kh * 32 + r + 8][kb2 + 4 + qa];
#pragma unroll
                        for (int s = 0; s < 3; s++) {
                            int n = wn + s * 8 + (lane >> 2);
                            uint32_t bhi[2], blo[2];
                            bhi[0] = BsHi[kh * 96 + n][kb2 + qa];
                            bhi[1] = BsHi[kh * 96 + n][kb2 + 4 + qa];
                            blo[0] = BsLo[kh * 96 + n][kb2 + qa];
                            blo[1] = BsLo[kh * 96 + n][kb2 + 4 + qa];
                            mma16(acc[s], ahi, bhi);
                            mma16(acc[s], alo, bhi);
                            mma16(acc[s], ahi, blo);
                        }
                    }
                    __syncthreads();
                }
                // spill & combine into sz0
                {
                    int rr = wm + (lane >> 2);
                    int cc = wn + (lane & 3) * 2;
#pragma unroll
                    for (int s = 0; s < 3; s++) {
                        zz[kh * 32 + rr][cc + s * 8]         = acc[s][0];
                        zz[kh * 32 + rr][cc + s * 8 + 1]     = acc[s][1];
                        zz[kh * 32 + rr + 8][cc + s * 8]     = acc[s][2];
                        zz[kh * 32 + rr + 8][cc + s * 8 + 1] = acc[s][3];
                    }
                }
                __syncthreads();
#pragma unroll
                for (int i = 0; i < 6; i++) {
                    int idx = i * 512 + tid;        // < 3072
                    int bl = idx / 96, c = idx - bl * 96;
                    sz0[bl][c] = zz[bl][c] + zz[32 + bl][c];
                }
                __syncthreads();
            } else {
                // 1-term bf16 GEMM on small delta: zd = delta @ Wpack_hi
                float acc[3][4];
#pragma unroll
                for (int s = 0; s < 3; s++)
#pragma unroll
                    for (int i = 0; i < 4; i++) acc[s][i] = 0.f;
                for (int it = 0; it < 8; it++) {
                    int kk = kk0 + it * 32;
                    float4 v = *(const float4*)&Ag[(m0 + lm) * HH + kk + lk];
                    AsHi[kh * 32 + lm][(lk >> 1) + 0] = pack_bf2(v.x, v.y);
                    AsHi[kh * 32 + lm][(lk >> 1) + 1] = pack_bf2(v.z, v.w);
#pragma unroll
                    for (int i = 0; i < 6; i++) {
                        int idx = i * 256 + ltid;
                        int n = idx >> 4, kq = idx & 15;
                        BsHi[kh * 96 + n][kq] = g_WBHi[(hg * 96 + n) * 256 + (kk >> 1) + kq];
                    }
                    __syncthreads();
#pragma unroll
                    for (int kb2 = 0; kb2 < 16; kb2 += 8) {
                        uint32_t ahi[4];
                        ahi[0] = AsHi[kh * 32 + r][kb2 + qa];
                        ahi[1] = AsHi[kh * 32 + r + 8][kb2 + qa];
                        ahi[2] = AsHi[kh * 32 + r][kb2 + 4 + qa];
                        ahi[3] = AsHi[kh * 32 + r + 8][kb2 + 4 + qa];
#pragma unroll
                        for (int s = 0; s < 3; s++) {
                            int n = wn + s * 8 + (lane >> 2);
                            uint32_t bhi[2];
                            bhi[0] = BsHi[kh * 96 + n][kb2 + qa];
                            bhi[1] = BsHi[kh * 96 + n][kb2 + 4 + qa];
                            mma16(acc[s], ahi, bhi);
                        }
                    }
                    __syncthreads();
                }
                {
                    int rr = wm + (lane >> 2);
                    int cc = wn + (lane & 3) * 2;
#pragma unroll
                    for (int s = 0; s < 3; s++) {
                        zz[kh * 32 + rr][cc + s * 8]         = acc[s][0];
                        zz[kh * 32 + rr][cc + s * 8 + 1]     = acc[s][1];
                        zz[kh * 32 + rr + 8][cc + s * 8]     = acc[s][2];
                        zz[kh * 32 + rr + 8][cc + s * 8 + 1] = acc[s][3];
                    }
                }
                __syncthreads();
            }

            // ---- fused RK epilogue (32b x 32h slice) ----
#pragma unroll
            for (int p = 0; p < 2; p++) {
                int idx = p * 512 + tid;            // 0..1023
                int bl = idx >> 5, hh = idx & 31;
                int b = m0 + bl, h = h0 + hh;
                int gi = b * HH + h;
                float zg, zd, zt;
                if (stage == 0) {
                    zg = sz0[bl][hh];
                    zd = sz0[bl][32 + hh];
                    zt = sz0[bl][64 + hh];
                } else {
                    zg = sz0[bl][hh]      + zz[bl][hh]      + zz[32 + bl][hh];
                    zd = sz0[bl][32 + hh] + zz[bl][32 + hh] + zz[32 + bl][32 + hh];
                    zt = sz0[bl][64 + hh] + zz[bl][64 + hh] + zz[32 + bl][64 + hh];
                }
                float gate = zg + sbase[bl][hh];
                float dyn  = zd + sbase[bl][32 + hh];
                float tau  = softplusf(zt + b_tau[h]);
                float hsv  = (stage == 0) ? g_h[gi] : (g_h[gi] + Ag[gi]);
                float kd   = (sigmoidf(gate) * tanhf(dyn) - hsv) / (tau + g_leak[h] + 1e-6f);
                float dt   = x_dts[b * TT + t];
                if (stage == 0) {
                    g_k1[gi] = kd;
                    g_dA[gi] = dt * kd * (1.f / 3.f);
                } else if (stage == 1) {
                    g_k2[gi] = kd;
                    g_dB[gi] = dt * (kd - g_k1[gi] * (1.f / 3.f));
                } else if (stage == 2) {
                    g_k3[gi] = kd;
                    g_dA[gi] = dt * (g_k1[gi] - g_k2[gi] + kd);
                } else {
                    g_h[gi] = g_h[gi] + dt * (g_k1[gi] + 3.f * g_k2[gi] + 3.f * g_k3[gi] + kd) * 0.125f;
                }
            }
            gbar(gid, 16);
        }
    }

    // ===== final projection =====
    {
        int b = bid * 2 + (tid >> 8);
        int lt = tid & 255;
        if (lt < OO) {
            float acc = b_fc[lt];
#pragma unroll 8
            for (int k = 0; k < HH; k++) acc += g_h[b * HH + k] * W_fc[k * OO + lt];
            out[b * OO + lt] = acc;
        }
    }
}

// ---------------- launch ----------------
extern "C" void kernel_launch(void* const* d_in, const int* in_sizes, int n_in,
                              void* d_out, int out_size) {
    const float* x_states = (const float*)d_in[0];
    const float* x_dts    = (const float*)d_in[1];
    const float* Wq    = (const float*)d_in[2];
    const float* bq    = (const float*)d_in[3];
    const float* Wk    = (const float*)d_in[4];
    const float* bk    = (const float*)d_in[5];
    const float* Wv    = (const float*)d_in[6];
    const float* bv    = (const float*)d_in[7];
    const float* W_gd  = (const float*)d_in[8];
    const float* b_gd  = (const float*)d_in[9];
    const float* W_tau = (const float*)d_in[10];
    const float* b_tau = (const float*)d_in[11];
    const float* gleak = (const float*)d_in[12];
    const float* cm    = (const float*)d_in[13];
    const float* W_fc  = (const float*)d_in[14];
    const float* b_fc  = (const float*)d_in[15];
    float* out = (float*)d_out;

    cudaFuncSetAttribute(mega, cudaFuncAttributeMaxDynamicSharedMemorySize, SMEM_BYTES);
    mega<<<NBLK, NTHR, SMEM_BYTES>>>(x_states, x_dts, Wq, bq, Wk, bk, Wv, bv,
                                     W_gd, b_gd, W_tau, b_tau, gleak, cm,
                                     W_fc, b_fc, out);
}

// round 8
// speedup vs baseline: 1.3050x; 1.3050x over previous
#include <cuda_runtime.h>
#include <cuda_bf16.h>
#include <math.h>
#include <stdint.h>

#define BB 256
#define TT 128
#define DD 64
#define HH 512
#define AA 128
#define OO 32
#define NBLK 128
#define NTHR 512

__device__ float g_K[BB * TT * AA];
__device__ float g_V[BB * TT * AA];
__device__ uint32_t g_WBLo[16 * 96 * 256];  // per-hg lo residual, bf16x2 [hg][n][kq]
__device__ float g_ctx[BB * AA];
__device__ float g_h[BB * HH];
__device__ uint32_t g_dA[BB * 256];         // packed bf16x2 deltas
__device__ uint32_t g_dB[BB * 256];
__device__ unsigned g_cnt[8];
__device__ volatile unsigned g_gen[8];

__device__ __forceinline__ float softplusf(float x) {
    return (x > 20.f) ? x : log1pf(expf(x));
}
__device__ __forceinline__ float sigmoidf(float x) {
    return 1.f / (1.f + expf(-x));
}
__device__ __forceinline__ float bfr(float x) {
    return __bfloat162float(__float2bfloat16(x));
}
__device__ __forceinline__ void mma16(float* d, const uint32_t* a, const uint32_t* b) {
    asm volatile(
        "mma.sync.aligned.m16n8k16.row.col.f32.bf16.bf16.f32 "
        "{%0,%1,%2,%3},{%4,%5,%6,%7},{%8,%9},{%0,%1,%2,%3};"
        : "+f"(d[0]), "+f"(d[1]), "+f"(d[2]), "+f"(d[3])
        : "r"(a[0]), "r"(a[1]), "r"(a[2]), "r"(a[3]), "r"(b[0]), "r"(b[1]));
}
__device__ __forceinline__ uint32_t pack_bf2(float a, float b) {
    __nv_bfloat162 t = __floats2bfloat162_rn(a, b);
    return *(uint32_t*)&t;
}

__device__ __forceinline__ void gbar(int idx) {
    __threadfence();
    __syncthreads();
    if (threadIdx.x == 0) {
        unsigned gen = g_gen[idx];
        if (atomicAdd(&g_cnt[idx], 1u) == 15u) {
            g_cnt[idx] = 0;
            __threadfence();
            g_gen[idx] = gen + 1;
        } else {
            while (g_gen[idx] == gen) __nanosleep(32);
        }
        __threadfence();
    }
    __syncthreads();
}

// smem map (bytes):
//  O_W  : u32 Ws[96][260]  resident weight hi (99840)
//  O_A  : u32 AsHi[32][260] (33280)   | kv hrow[32][516]f | attn scratch
//  O_AL : u32 AsLo[32][260] (33280)
//  O_Z  : float zz[64][96] / BsLo[192][17] / cz[32][192]  (24576)
//  O_SB : float sbase[32][64] (8192)
//  O_SZ : float sz0[32][96] (12288)
#define O_W  0
#define O_A  99840
#define O_AL 133120
#define O_Z  166400
#define O_SB 190976
#define O_SZ 199168
#define SMEM_BYTES 211456

typedef uint32_t U17[17];

__global__ void __launch_bounds__(NTHR, 1) mega(
    const float* __restrict__ x_states, const float* __restrict__ x_dts,
    const float* __restrict__ Wq, const float* __restrict__ bq,
    const float* __restrict__ Wk, const float* __restrict__ bk,
    const float* __restrict__ Wv, const float* __restrict__ bv,
    const float* __restrict__ W_gd, const float* __restrict__ b_gd,
    const float* __restrict__ W_tau, const float* __restrict__ b_tau,
    const float* __restrict__ gleak, const float* __restrict__ cm,
    const float* __restrict__ W_fc, const float* __restrict__ b_fc,
    float* __restrict__ out)
{
    extern __shared__ char smraw[];
    __shared__ float sleak[32], sbtau[32];
    uint32_t* Ws   = (uint32_t*)(smraw + O_W);
    uint32_t* AsHi = (uint32_t*)(smraw + O_A);
    uint32_t* AsLo = (uint32_t*)(smraw + O_AL);
    float (*zz)[96]    = (float(*)[96])(smraw + O_Z);
    float (*sbase)[64] = (float(*)[64])(smraw + O_SB);
    float (*sz0)[96]   = (float(*)[96])(smraw + O_SZ);

    int bid = blockIdx.x, tid = threadIdx.x;
    int lane = tid & 31, wid = tid >> 5;
    int gid = bid >> 4, hg = bid & 15;
    int m0 = gid * 32, h0 = hg * 32;

    // ===== prep (group-local; no global barrier) =====
    if (tid < 32) {
        sleak[tid] = softplusf(cm[h0 + tid]) + softplusf(gleak[h0 + tid]);
        sbtau[tid] = b_tau[h0 + tid];
    }
    for (int idx = tid; idx < 96 * 256; idx += NTHR) {
        int n = idx >> 8, kq = idx & 255, k0 = kq * 2;
        float w0, w1;
        if (n < 32)      { w0 = W_gd[(64 + k0) * 1024 + h0 + n];       w1 = W_gd[(65 + k0) * 1024 + h0 + n]; }
        else if (n < 64) { w0 = W_gd[(64 + k0) * 1024 + 512 + h0 + n - 32]; w1 = W_gd[(65 + k0) * 1024 + 512 + h0 + n - 32]; }
        else             { w0 = W_tau[k0 * 512 + h0 + n - 64];         w1 = W_tau[(k0 + 1) * 512 + h0 + n - 64]; }
        float a = bfr(w0), b = bfr(w1);
        Ws[n * 260 + kq] = pack_bf2(a, b);
        g_WBLo[(hg * 96 + n) * 256 + kq] = pack_bf2(w0 - a, w1 - b);
    }
    for (int idx = tid; idx < 32 * HH; idx += NTHR) g_h[m0 * HH + idx] = 0.f;
    gbar(gid);

    // register-resident RK state (thread owns (b,h) = (m0+((p*512+tid)>>5), h0+((p*512+tid)&31)))
    float hreg[2] = {0.f, 0.f}, rk1[2], rk2[2], rk3[2], dd[2];
    int kh = wid >> 3, wl = wid & 7;
    int wm = (wl >> 2) * 16, wn = (wl & 3) * 24;
    int r = wm + (lane >> 2), qa = lane & 3;

    for (int t = 0; t < TT; t++) {
        // ---- KV: row t-1 = g_h @ [Wk|Wv]; 32b x 16n per block ----
        if (t > 0) {
            float (*hrow)[516] = (float(*)[516])(smraw + O_A);
#pragma unroll
            for (int i = 0; i < 8; i++) {
                int idx = i * 512 + tid;
                int rr = idx >> 7, c4 = (idx & 127) << 2;
                *(float4*)&hrow[rr][c4] = *(const float4*)&g_h[(m0 + rr) * HH + c4];
            }
            __syncthreads();
            int tx = tid & 15, ty = tid >> 4;
            int nn = hg * 16 + tx, ncol = nn & 127;
            const float* W = (nn < 128) ? Wk : Wv;
            float acc = (nn < 128) ? bk[ncol] : bv[ncol];
            const float* hr = hrow[ty];
#pragma unroll 8
            for (int k = 0; k < HH; k++) acc += hr[k] * W[k * AA + ncol];
            float* dst = (nn < 128) ? g_K : g_V;
            dst[((m0 + ty) * TT + (t - 1)) * AA + ncol] = acc;
            gbar(gid);
        }

        // ---- ATTN: 2 batches per block ----
        {
            float* aq   = (float*)(smraw + O_A);
            float* asc  = aq + 256;
            float* actx = asc + 256;
            float* axs  = actx + 512;
            float* ared = axs + 128;
            int hB = tid >> 8, lt = tid & 255;
            int b = bid * 2 + hB;
            if (t == 0) {
                if (lt < 128) g_ctx[b * AA + lt] = 0.f;
            } else {
                if (lt < DD) axs[hB * 64 + lt] = x_states[(b * TT + t) * DD + lt];
                __syncthreads();
                if (lt < 128) {
                    float qv = bq[lt];
#pragma unroll 16
                    for (int d = 0; d < DD; d++) qv += axs[hB * 64 + d] * Wq[d * AA + lt];
                    aq[hB * 128 + lt] = qv;
                }
                __syncthreads();
                float s = -1e30f;
                if (lt < t) {
                    const float4* Kp = (const float4*)&g_K[(b * TT + lt) * AA];
                    const float* qh = &aq[hB * 128];
                    float dot = 0.f;
#pragma unroll 8
                    for (int a4 = 0; a4 < AA / 4; a4++) {
                        float4 kv = Kp[a4];
                        dot += kv.x * qh[4 * a4] + kv.y * qh[4 * a4 + 1] +
                               kv.z * qh[4 * a4 + 2] + kv.w * qh[4 * a4 + 3];
                    }
                    s = dot * (1.f / 11.313708498984761f);
                }
                float m = s;
#pragma unroll
                for (int o = 16; o > 0; o >>= 1) m = fmaxf(m, __shfl_xor_sync(~0u, m, o));
                if (lane == 0) ared[hB * 8 + (wid & 7)] = m;
                __syncthreads();
                m = ared[hB * 8];
#pragma unroll
                for (int i = 1; i < 8; i++) m = fmaxf(m, ared[hB * 8 + i]);
                float e = (lt < t) ? expf(s - m) : 0.f;
                float su = e;
#pragma unroll
                for (int o = 16; o > 0; o >>= 1) su += __shfl_xor_sync(~0u, su, o);
                __syncthreads();
                if (lane == 0) ared[hB * 8 + (wid & 7)] = su;
                __syncthreads();
                su = 0.f;
#pragma unroll
                for (int i = 0; i < 8; i++) su += ared[hB * 8 + i];
                if (lt < 128) asc[hB * 128 + lt] = e / su;
                __syncthreads();
                {
                    int a = lt & 127, th = lt >> 7;
                    float c = 0.f;
                    for (int sx = th; sx < t; sx += 2)
                        c += asc[hB * 128 + sx] * g_V[(b * TT + sx) * AA + a];
                    actx[(hB * 2 + th) * 128 + a] = c;
                }
                __syncthreads();
                if (lt < 128)
                    g_ctx[b * AA + lt] = actx[hB * 256 + lt] + actx[hB * 256 + 128 + lt];
            }
            gbar(gid);
        }

        // ---- 4 RK stages ----
        for (int stage = 0; stage < 4; stage++) {
            float acc[3][4];
#pragma unroll
            for (int s = 0; s < 3; s++)
#pragma unroll
                for (int i = 0; i < 4; i++) acc[s][i] = 0.f;

            if (stage == 0) {
                // cz staging + A(h) staging
                float (*cz)[192] = (float(*)[192])(smraw + O_Z);
#pragma unroll
                for (int i = 0; i < 12; i++) {
                    int idx = i * 512 + tid;
                    int bl = idx / 192, k = idx - bl * 192;
                    cz[bl][k] = (k < 64) ? x_states[((m0 + bl) * TT + t) * DD + k]
                                         : g_ctx[(m0 + bl) * AA + (k - 64)];
                }
#pragma unroll
                for (int i = 0; i < 8; i++) {
                    int idx = i * 512 + tid;
                    int m = idx >> 7, f4 = idx & 127;
                    float4 v = *(const float4*)&g_h[(m0 + m) * HH + f4 * 4];
                    float ax = bfr(v.x), ay = bfr(v.y), az = bfr(v.z), aw = bfr(v.w);
                    int o = m * 260 + f4 * 2;
                    *(uint2*)&AsHi[o] = make_uint2(pack_bf2(ax, ay), pack_bf2(az, aw));
                    *(uint2*)&AsLo[o] = make_uint2(pack_bf2(v.x - ax, v.y - ay),
                                                   pack_bf2(v.z - az, v.w - aw));
                }
                __syncthreads();
                // base GEMM -> sbase
                {
                    int tx2 = tid & 63, ty2 = tid >> 6;
                    int col = (tx2 < 32) ? (h0 + tx2) : (512 + h0 + tx2 - 32);
                    float a0 = 0, a1 = 0, a2 = 0, a3 = 0;
#pragma unroll 8
                    for (int k = 0; k < 64; k++) {
                        float w = W_gd[k * 1024 + col];
                        a0 += cz[ty2 * 4 + 0][k] * w; a1 += cz[ty2 * 4 + 1][k] * w;
                        a2 += cz[ty2 * 4 + 2][k] * w; a3 += cz[ty2 * 4 + 3][k] * w;
                    }
#pragma unroll 8
                    for (int k = 64; k < 192; k++) {
                        float w = W_gd[(k + 512) * 1024 + col];
                        a0 += cz[ty2 * 4 + 0][k] * w; a1 += cz[ty2 * 4 + 1][k] * w;
                        a2 += cz[ty2 * 4 + 2][k] * w; a3 += cz[ty2 * 4 + 3][k] * w;
                    }
                    float bg = b_gd[col];
                    sbase[ty2 * 4 + 0][tx2] = a0 + bg; sbase[ty2 * 4 + 1][tx2] = a1 + bg;
                    sbase[ty2 * 4 + 2][tx2] = a2 + bg; sbase[ty2 * 4 + 3][tx2] = a3 + bg;
                }
                __syncthreads();
                // hi pass: (ahi+alo)*bhi, W resident, no syncs
#pragma unroll
                for (int it = 0; it < 8; it++) {
                    int kq0 = kh * 128 + it * 16;
#pragma unroll
                    for (int kb2 = 0; kb2 < 16; kb2 += 8) {
                        uint32_t ahi[4], alo[4];
                        ahi[0] = AsHi[r * 260 + kq0 + kb2 + qa];
                        ahi[1] = AsHi[(r + 8) * 260 + kq0 + kb2 + qa];
                        ahi[2] = AsHi[r * 260 + kq0 + kb2 + 4 + qa];
                        ahi[3] = AsHi[(r + 8) * 260 + kq0 + kb2 + 4 + qa];
                        alo[0] = AsLo[r * 260 + kq0 + kb2 + qa];
                        alo[1] = AsLo[(r + 8) * 260 + kq0 + kb2 + qa];
                        alo[2] = AsLo[r * 260 + kq0 + kb2 + 4 + qa];
                        alo[3] = AsLo[(r + 8) * 260 + kq0 + kb2 + 4 + qa];
#pragma unroll
                        for (int s = 0; s < 3; s++) {
                            int n = wn + s * 8 + (lane >> 2);
                            uint32_t bhi[2];
                            bhi[0] = Ws[n * 260 + kq0 + kb2 + qa];
                            bhi[1] = Ws[n * 260 + kq0 + kb2 + 4 + qa];
                            mma16(acc[s], ahi, bhi);
                            mma16(acc[s], alo, bhi);
                        }
                    }
                }
                // lo pass: ahi*blo, chunked
                U17* BsLo = (U17*)(smraw + O_Z);
                __syncthreads();
                for (int it = 0; it < 8; it++) {
#pragma unroll
                    for (int i = 0; i < 6; i++) {
                        int idx = i * 512 + tid;
                        int n192 = idx >> 4, kq = idx & 15;
                        int khh = (n192 >= 96), n = n192 - khh * 96;
                        BsLo[n192][kq] = g_WBLo[(hg * 96 + n) * 256 + khh * 128 + it * 16 + kq];
                    }
                    __syncthreads();
                    int kq0 = kh * 128 + it * 16;
#pragma unroll
                    for (int kb2 = 0; kb2 < 16; kb2 += 8) {
                        uint32_t ahi[4];
                        ahi[0] = AsHi[r * 260 + kq0 + kb2 + qa];
                        ahi[1] = AsHi[(r + 8) * 260 + kq0 + kb2 + qa];
                        ahi[2] = AsHi[r * 260 + kq0 + kb2 + 4 + qa];
                        ahi[3] = AsHi[(r + 8) * 260 + kq0 + kb2 + 4 + qa];
#pragma unroll
                        for (int s = 0; s < 3; s++) {
                            int n = wn + s * 8 + (lane >> 2);
                            uint32_t blo[2];
                            blo[0] = BsLo[kh * 96 + n][kb2 + qa];
                            blo[1] = BsLo[kh * 96 + n][kb2 + 4 + qa];
                            mma16(acc[s], ahi, blo);
                        }
                    }
                    __syncthreads();
                }
            } else {
                // delta stage: A from packed deltas, W resident, single term
                const uint32_t* Dg = (stage == 2) ? g_dB : g_dA;
#pragma unroll
                for (int i = 0; i < 4; i++) {
                    int idx = i * 512 + tid;
                    int m = idx >> 6, q4 = idx & 63;
                    uint4 v = ((const uint4*)&Dg[(m0 + m) * 256])[q4];
                    *(uint4*)&AsHi[m * 260 + q4 * 4] = v;
                }
                __syncthreads();
#pragma unroll
                for (int it = 0; it < 8; it++) {
                    int kq0 = kh * 128 + it * 16;
#pragma unroll
                    for (int kb2 = 0; kb2 < 16; kb2 += 8) {
                        uint32_t ahi[4];
                        ahi[0] = AsHi[r * 260 + kq0 + kb2 + qa];
                        ahi[1] = AsHi[(r + 8) * 260 + kq0 + kb2 + qa];
                        ahi[2] = AsHi[r * 260 + kq0 + kb2 + 4 + qa];
                        ahi[3] = AsHi[(r + 8) * 260 + kq0 + kb2 + 4 + qa];
#pragma unroll
                        for (int s = 0; s < 3; s++) {
                            int n = wn + s * 8 + (lane >> 2);
                            uint32_t bhi[2];
                            bhi[0] = Ws[n * 260 + kq0 + kb2 + qa];
                            bhi[1] = Ws[n * 260 + kq0 + kb2 + 4 + qa];
                            mma16(acc[s], ahi, bhi);
                        }
                    }
                }
                __syncthreads();
            }

            // spill zz
            {
                int rr = wm + (lane >> 2), cc = wn + (lane & 3) * 2;
#pragma unroll
                for (int s = 0; s < 3; s++) {
                    zz[kh * 32 + rr][cc + s * 8]         = acc[s][0];
                    zz[kh * 32 + rr][cc + s * 8 + 1]     = acc[s][1];
                    zz[kh * 32 + rr + 8][cc + s * 8]     = acc[s][2];
                    zz[kh * 32 + rr + 8][cc + s * 8 + 1] = acc[s][3];
                }
            }
            __syncthreads();
            if (stage == 0) {
#pragma unroll
                for (int i = 0; i < 6; i++) {
                    int idx = i * 512 + tid;
                    int bl = idx / 96, c = idx - bl * 96;
                    sz0[bl][c] = zz[bl][c] + zz[32 + bl][c];
                }
                __syncthreads();
            }

            // fused RK epilogue (register-resident state)
#pragma unroll
            for (int p = 0; p < 2; p++) {
                int idx = p * 512 + tid;
                int bl = idx >> 5, hh = idx & 31;
                int b = m0 + bl;
                float zg, zdn, zt;
                if (stage == 0) {
                    zg = sz0[bl][hh]; zdn = sz0[bl][32 + hh]; zt = sz0[bl][64 + hh];
                } else {
                    zg  = sz0[bl][hh]      + zz[bl][hh]      + zz[32 + bl][hh];
                    zdn = sz0[bl][32 + hh] + zz[bl][32 + hh] + zz[32 + bl][32 + hh];
                    zt  = sz0[bl][64 + hh] + zz[bl][64 + hh] + zz[32 + bl][64 + hh];
                }
                float gate = zg + sbase[bl][hh];
                float dyn  = zdn + sbase[bl][32 + hh];
                float tau  = softplusf(zt + sbtau[hh]);
                float hsv  = (stage == 0) ? hreg[p] : (hreg[p] + dd[p]);
                float kd   = (sigmoidf(gate) * tanhf(dyn) - hsv) / (tau + sleak[hh] + 1e-6f);
                float dt   = x_dts[b * TT + t];
                if (stage == 3) {
                    hreg[p] += dt * (rk1[p] + 3.f * rk2[p] + 3.f * rk3[p] + kd) * 0.125f;
                    g_h[b * HH + h0 + hh] = hreg[p];
                } else {
                    float dnew;
                    if (stage == 0)      { rk1[p] = kd; dnew = dt * kd * (1.f / 3.f); }
                    else if (stage == 1) { rk2[p] = kd; dnew = dt * (kd - rk1[p] * (1.f / 3.f)); }
                    else                 { rk3[p] = kd; dnew = dt * (rk1[p] - rk2[p] + kd); }
                    dd[p] = dnew;
                    float oth = __shfl_xor_sync(~0u, dnew, 1);
                    if (!(tid & 1)) {
                        uint32_t pk = pack_bf2(dnew, oth);
                        if (stage == 1) g_dB[b * 256 + ((h0 + hh) >> 1)] = pk;
                        else            g_dA[b * 256 + ((h0 + hh) >> 1)] = pk;
                    }
                }
            }
            gbar(gid);
        }
    }

    // ===== final projection =====
    {
        int b = bid * 2 + (tid >> 8);
        int lt = tid & 255;
        if (lt < OO) {
            float acc = b_fc[lt];
#pragma unroll 8
            for (int k = 0; k < HH; k++) acc += g_h[b * HH + k] * W_fc[k * OO + lt];
            out[b * OO + lt] = acc;
        }
    }
}

extern "C" void kernel_launch(void* const* d_in, const int* in_sizes, int n_in,
                              void* d_out, int out_size) {
    const float* x_states = (const float*)d_in[0];
    const float* x_dts    = (const float*)d_in[1];
    const float* Wq = (const float*)d_in[2];  const float* bq = (const float*)d_in[3];
    const float* Wk = (const float*)d_in[4];  const float* bk = (const float*)d_in[5];
    const float* Wv = (const float*)d_in[6];  const float* bv = (const float*)d_in[7];
    const float* W_gd = (const float*)d_in[8]; const float* b_gd = (const float*)d_in[9];
    const float* W_tau = (const float*)d_in[10]; const float* b_tau = (const float*)d_in[11];
    const float* gleak = (const float*)d_in[12]; const float* cm = (const float*)d_in[13];
    const float* W_fc = (const float*)d_in[14]; const float* b_fc = (const float*)d_in[15];
    float* out = (float*)d_out;

    cudaFuncSetAttribute(mega, cudaFuncAttributeMaxDynamicSharedMemorySize, SMEM_BYTES);
    mega<<<NBLK, NTHR, SMEM_BYTES>>>(x_states, x_dts, Wq, bq, Wk, bk, Wv, bv,
                                     W_gd, b_gd, W_tau, b_tau, gleak, cm,
                                     W_fc, b_fc, out);
}

// round 9
// speedup vs baseline: 1.3780x; 1.0560x over previous
#include <cuda_runtime.h>
#include <cuda_bf16.h>
#include <math.h>
#include <stdint.h>

#define BB 256
#define TT 128
#define DD 64
#define HH 512
#define AA 128
#define OO 32
#define NBLK 128
#define NTHR 512

__device__ float g_K[BB * TT * AA];
__device__ float g_V[BB * TT * AA];
__device__ uint32_t g_WBLo[16 * 96 * 256];  // per-hg lo residual, bf16x2 [hg][n][kq]
__device__ float g_ctx[BB * AA];
__device__ float g_h[BB * HH];
__device__ uint32_t g_dA[BB * 256];         // packed bf16x2 deltas
__device__ uint32_t g_dB[BB * 256];
__device__ unsigned g_cnt[8];
__device__ volatile unsigned g_gen[8];

__device__ __forceinline__ float softplusf(float x) {
    return (x > 20.f) ? x : log1pf(expf(x));
}
__device__ __forceinline__ float sigmoidf(float x) {
    return 1.f / (1.f + expf(-x));
}
__device__ __forceinline__ float bfr(float x) {
    return __bfloat162float(__float2bfloat16(x));
}
__device__ __forceinline__ void mma16(float* d, const uint32_t* a, const uint32_t* b) {
    asm volatile(
        "mma.sync.aligned.m16n8k16.row.col.f32.bf16.bf16.f32 "
        "{%0,%1,%2,%3},{%4,%5,%6,%7},{%8,%9},{%0,%1,%2,%3};"
        : "+f"(d[0]), "+f"(d[1]), "+f"(d[2]), "+f"(d[3])
        : "r"(a[0]), "r"(a[1]), "r"(a[2]), "r"(a[3]), "r"(b[0]), "r"(b[1]));
}
__device__ __forceinline__ uint32_t pack_bf2(float a, float b) {
    __nv_bfloat162 t = __floats2bfloat162_rn(a, b);
    return *(uint32_t*)&t;
}

// CG-style barrier: fences only in thread 0 (bar.sync provides the block edge)
__device__ __forceinline__ void gbar(int idx) {
    __syncthreads();
    if (threadIdx.x == 0) {
        __threadfence();                      // release
        unsigned gen = g_gen[idx];
        if (atomicAdd(&g_cnt[idx], 1u) == 15u) {
            g_cnt[idx] = 0;
            __threadfence();
            g_gen[idx] = gen + 1;
        } else {
            while (g_gen[idx] == gen) __nanosleep(32);
            __threadfence();                  // acquire
        }
    }
    __syncthreads();
}

// smem map (bytes) — unchanged from R8
#define O_W  0
#define O_A  99840
#define O_AL 133120
#define O_Z  166400
#define O_SB 190976
#define O_SZ 199168
#define SMEM_BYTES 211456

typedef uint32_t U17[17];

__global__ void __launch_bounds__(NTHR, 1) mega(
    const float* __restrict__ x_states, const float* __restrict__ x_dts,
    const float* __restrict__ Wq, const float* __restrict__ bq,
    const float* __restrict__ Wk, const float* __restrict__ bk,
    const float* __restrict__ Wv, const float* __restrict__ bv,
    const float* __restrict__ W_gd, const float* __restrict__ b_gd,
    const float* __restrict__ W_tau, const float* __restrict__ b_tau,
    const float* __restrict__ gleak, const float* __restrict__ cm,
    const float* __restrict__ W_fc, const float* __restrict__ b_fc,
    float* __restrict__ out)
{
    extern __shared__ char smraw[];
    __shared__ float sleak[32], sbtau[32];
    uint32_t* Ws   = (uint32_t*)(smraw + O_W);
    uint32_t* AsHi = (uint32_t*)(smraw + O_A);
    uint32_t* AsLo = (uint32_t*)(smraw + O_AL);
    float (*zz)[96]    = (float(*)[96])(smraw + O_Z);
    float (*sbase)[64] = (float(*)[64])(smraw + O_SB);
    float (*sz0)[96]   = (float(*)[96])(smraw + O_SZ);

    int bid = blockIdx.x, tid = threadIdx.x;
    int lane = tid & 31, wid = tid >> 5;
    int gid = bid >> 4, hg = bid & 15;
    int m0 = gid * 32, h0 = hg * 32;

    // ===== prep (group-local) =====
    if (tid < 32) {
        sleak[tid] = softplusf(cm[h0 + tid]) + softplusf(gleak[h0 + tid]);
        sbtau[tid] = b_tau[h0 + tid];
    }
    for (int idx = tid; idx < 96 * 256; idx += NTHR) {
        int n = idx >> 8, kq = idx & 255, k0 = kq * 2;
        float w0, w1;
        if (n < 32)      { w0 = W_gd[(64 + k0) * 1024 + h0 + n];       w1 = W_gd[(65 + k0) * 1024 + h0 + n]; }
        else if (n < 64) { w0 = W_gd[(64 + k0) * 1024 + 512 + h0 + n - 32]; w1 = W_gd[(65 + k0) * 1024 + 512 + h0 + n - 32]; }
        else             { w0 = W_tau[k0 * 512 + h0 + n - 64];         w1 = W_tau[(k0 + 1) * 512 + h0 + n - 64]; }
        float a = bfr(w0), b = bfr(w1);
        Ws[n * 260 + kq] = pack_bf2(a, b);
        g_WBLo[(hg * 96 + n) * 256 + kq] = pack_bf2(w0 - a, w1 - b);
    }
    for (int idx = tid; idx < 32 * HH; idx += NTHR) g_h[m0 * HH + idx] = 0.f;
    gbar(gid);

    float hreg[2] = {0.f, 0.f}, rk1[2], rk2[2], rk3[2], dd[2];
    int kh = wid >> 3, wl = wid & 7;
    int wm = (wl >> 2) * 16, wn = (wl & 3) * 24;
    int r = wm + (lane >> 2), qa = lane & 3;

    for (int t = 0; t < TT; t++) {
        // ---- KV: row t-1 = g_h @ [Wk|Wv]; 32b x 16n per block ----
        if (t > 0) {
            float (*hrow)[516] = (float(*)[516])(smraw + O_A);
#pragma unroll
            for (int i = 0; i < 8; i++) {
                int idx = i * 512 + tid;
                int rr = idx >> 7, c4 = (idx & 127) << 2;
                *(float4*)&hrow[rr][c4] = *(const float4*)&g_h[(m0 + rr) * HH + c4];
            }
            __syncthreads();
            int tx = tid & 15, ty = tid >> 4;
            int nn = hg * 16 + tx, ncol = nn & 127;
            const float* W = (nn < 128) ? Wk : Wv;
            float acc = (nn < 128) ? bk[ncol] : bv[ncol];
            const float* hr = hrow[ty];
#pragma unroll 16
            for (int k = 0; k < HH; k++) acc += hr[k] * W[k * AA + ncol];
            float* dst = (nn < 128) ? g_K : g_V;
            dst[((m0 + ty) * TT + (t - 1)) * AA + ncol] = acc;
            gbar(gid);
        }

        // ---- ATTN: 2 batches per block ----
        {
            float* aq   = (float*)(smraw + O_A);
            float* asc  = aq + 256;
            float* actx = asc + 256;
            float* axs  = actx + 512;
            float* ared = axs + 128;
            int hB = tid >> 8, lt = tid & 255;
            int b = bid * 2 + hB;
            if (t == 0) {
                if (lt < 128) g_ctx[b * AA + lt] = 0.f;
            } else {
                if (lt < DD) axs[hB * 64 + lt] = x_states[(b * TT + t) * DD + lt];
                __syncthreads();
                if (lt < 128) {
                    float qv = bq[lt];
#pragma unroll 16
                    for (int d = 0; d < DD; d++) qv += axs[hB * 64 + d] * Wq[d * AA + lt];
                    aq[hB * 128 + lt] = qv;
                }
                __syncthreads();
                float s = -1e30f;
                if (lt < t) {
                    const float4* Kp = (const float4*)&g_K[(b * TT + lt) * AA];
                    const float* qh = &aq[hB * 128];
                    float dot = 0.f;
#pragma unroll 8
                    for (int a4 = 0; a4 < AA / 4; a4++) {
                        float4 kv = Kp[a4];
                        dot += kv.x * qh[4 * a4] + kv.y * qh[4 * a4 + 1] +
                               kv.z * qh[4 * a4 + 2] + kv.w * qh[4 * a4 + 3];
                    }
                    s = dot * (1.f / 11.313708498984761f);
                }
                float m = s;
#pragma unroll
                for (int o = 16; o > 0; o >>= 1) m = fmaxf(m, __shfl_xor_sync(~0u, m, o));
                if (lane == 0) ared[hB * 8 + (wid & 7)] = m;
                __syncthreads();
                m = ared[hB * 8];
#pragma unroll
                for (int i = 1; i < 8; i++) m = fmaxf(m, ared[hB * 8 + i]);
                float e = (lt < t) ? expf(s - m) : 0.f;
                float su = e;
#pragma unroll
                for (int o = 16; o > 0; o >>= 1) su += __shfl_xor_sync(~0u, su, o);
                __syncthreads();
                if (lane == 0) ared[hB * 8 + (wid & 7)] = su;
                __syncthreads();
                su = 0.f;
#pragma unroll
                for (int i = 0; i < 8; i++) su += ared[hB * 8 + i];
                if (lt < 128) asc[hB * 128 + lt] = (lt < t) ? (e / su) : 0.f;  // zero-pad
                __syncthreads();
                {
                    int a = lt & 127, th = lt >> 7;
                    int tlim = (t + 7) & ~7;          // rounded-up bound, padded scores are 0
                    float c = 0.f;
#pragma unroll 8
                    for (int sx = th; sx < tlim; sx += 2)
                        c += asc[hB * 128 + sx] * g_V[(b * TT + sx) * AA + a];
                    actx[(hB * 2 + th) * 128 + a] = c;
                }
                __syncthreads();
                if (lt < 128)
                    g_ctx[b * AA + lt] = actx[hB * 256 + lt] + actx[hB * 256 + 128 + lt];
            }
            gbar(gid);
        }

        // ---- 4 RK stages ----
        for (int stage = 0; stage < 4; stage++) {
            float acc[3][4];
#pragma unroll
            for (int s = 0; s < 3; s++)
#pragma unroll
                for (int i = 0; i < 4; i++) acc[s][i] = 0.f;

            if (stage == 0) {
                float (*cz)[192] = (float(*)[192])(smraw + O_Z);
#pragma unroll
                for (int i = 0; i < 12; i++) {
                    int idx = i * 512 + tid;
                    int bl = idx / 192, k = idx - bl * 192;
                    cz[bl][k] = (k < 64) ? x_states[((m0 + bl) * TT + t) * DD + k]
                                         : g_ctx[(m0 + bl) * AA + (k - 64)];
                }
#pragma unroll
                for (int i = 0; i < 8; i++) {
                    int idx = i * 512 + tid;
                    int m = idx >> 7, f4 = idx & 127;
                    float4 v = *(const float4*)&g_h[(m0 + m) * HH + f4 * 4];
                    float ax = bfr(v.x), ay = bfr(v.y), az = bfr(v.z), aw = bfr(v.w);
                    int o = m * 260 + f4 * 2;
                    *(uint2*)&AsHi[o] = make_uint2(pack_bf2(ax, ay), pack_bf2(az, aw));
                    *(uint2*)&AsLo[o] = make_uint2(pack_bf2(v.x - ax, v.y - ay),
                                                   pack_bf2(v.z - az, v.w - aw));
                }
                __syncthreads();
                {
                    int tx2 = tid & 63, ty2 = tid >> 6;
                    int col = (tx2 < 32) ? (h0 + tx2) : (512 + h0 + tx2 - 32);
                    float a0 = 0, a1 = 0, a2 = 0, a3 = 0;
#pragma unroll 8
                    for (int k = 0; k < 64; k++) {
                        float w = W_gd[k * 1024 + col];
                        a0 += cz[ty2 * 4 + 0][k] * w; a1 += cz[ty2 * 4 + 1][k] * w;
                        a2 += cz[ty2 * 4 + 2][k] * w; a3 += cz[ty2 * 4 + 3][k] * w;
                    }
#pragma unroll 8
                    for (int k = 64; k < 192; k++) {
                        float w = W_gd[(k + 512) * 1024 + col];
                        a0 += cz[ty2 * 4 + 0][k] * w; a1 += cz[ty2 * 4 + 1][k] * w;
                        a2 += cz[ty2 * 4 + 2][k] * w; a3 += cz[ty2 * 4 + 3][k] * w;
                    }
                    float bg = b_gd[col];
                    sbase[ty2 * 4 + 0][tx2] = a0 + bg; sbase[ty2 * 4 + 1][tx2] = a1 + bg;
                    sbase[ty2 * 4 + 2][tx2] = a2 + bg; sbase[ty2 * 4 + 3][tx2] = a3 + bg;
                }
                __syncthreads();
#pragma unroll
                for (int it = 0; it < 8; it++) {
                    int kq0 = kh * 128 + it * 16;
#pragma unroll
                    for (int kb2 = 0; kb2 < 16; kb2 += 8) {
                        uint32_t ahi[4], alo[4];
                        ahi[0] = AsHi[r * 260 + kq0 + kb2 + qa];
                        ahi[1] = AsHi[(r + 8) * 260 + kq0 + kb2 + qa];
                        ahi[2] = AsHi[r * 260 + kq0 + kb2 + 4 + qa];
                        ahi[3] = AsHi[(r + 8) * 260 + kq0 + kb2 + 4 + qa];
                        alo[0] = AsLo[r * 260 + kq0 + kb2 + qa];
                        alo[1] = AsLo[(r + 8) * 260 + kq0 + kb2 + qa];
                        alo[2] = AsLo[r * 260 + kq0 + kb2 + 4 + qa];
                        alo[3] = AsLo[(r + 8) * 260 + kq0 + kb2 + 4 + qa];
#pragma unroll
                        for (int s = 0; s < 3; s++) {
                            int n = wn + s * 8 + (lane >> 2);
                            uint32_t bhi[2];
                            bhi[0] = Ws[n * 260 + kq0 + kb2 + qa];
                            bhi[1] = Ws[n * 260 + kq0 + kb2 + 4 + qa];
                            mma16(acc[s], ahi, bhi);
                            mma16(acc[s], alo, bhi);
                        }
                    }
                }
                U17* BsLo = (U17*)(smraw + O_Z);
                __syncthreads();
                for (int it = 0; it < 8; it++) {
#pragma unroll
                    for (int i = 0; i < 6; i++) {
                        int idx = i * 512 + tid;
                        int n192 = idx >> 4, kq = idx & 15;
                        int khh = (n192 >= 96), n = n192 - khh * 96;
                        BsLo[n192][kq] = g_WBLo[(hg * 96 + n) * 256 + khh * 128 + it * 16 + kq];
                    }
                    __syncthreads();
                    int kq0 = kh * 128 + it * 16;
#pragma unroll
                    for (int kb2 = 0; kb2 < 16; kb2 += 8) {
                        uint32_t ahi[4];
                        ahi[0] = AsHi[r * 260 + kq0 + kb2 + qa];
                        ahi[1] = AsHi[(r + 8) * 260 + kq0 + kb2 + qa];
                        ahi[2] = AsHi[r * 260 + kq0 + kb2 + 4 + qa];
                        ahi[3] = AsHi[(r + 8) * 260 + kq0 + kb2 + 4 + qa];
#pragma unroll
                        for (int s = 0; s < 3; s++) {
                            int n = wn + s * 8 + (lane >> 2);
                            uint32_t blo[2];
                            blo[0] = BsLo[kh * 96 + n][kb2 + qa];
                            blo[1] = BsLo[kh * 96 + n][kb2 + 4 + qa];
                            mma16(acc[s], ahi, blo);
                        }
                    }
                    __syncthreads();
                }
            } else {
                const uint32_t* Dg = (stage == 2) ? g_dB : g_dA;
#pragma unroll
                for (int i = 0; i < 4; i++) {
                    int idx = i * 512 + tid;
                    int m = idx >> 6, q4 = idx & 63;
                    uint4 v = ((const uint4*)&Dg[(m0 + m) * 256])[q4];
                    *(uint4*)&AsHi[m * 260 + q4 * 4] = v;
                }
                __syncthreads();
#pragma unroll
                for (int it = 0; it < 8; it++) {
                    int kq0 = kh * 128 + it * 16;
#pragma unroll
                    for (int kb2 = 0; kb2 < 16; kb2 += 8) {
                        uint32_t ahi[4];
                        ahi[0] = AsHi[r * 260 + kq0 + kb2 + qa];
                        ahi[1] = AsHi[(r + 8) * 260 + kq0 + kb2 + qa];
                        ahi[2] = AsHi[r * 260 + kq0 + kb2 + 4 + qa];
                        ahi[3] = AsHi[(r + 8) * 260 + kq0 + kb2 + 4 + qa];
#pragma unroll
                        for (int s = 0; s < 3; s++) {
                            int n = wn + s * 8 + (lane >> 2);
                            uint32_t bhi[2];
                            bhi[0] = Ws[n * 260 + kq0 + kb2 + qa];
                            bhi[1] = Ws[n * 260 + kq0 + kb2 + 4 + qa];
                            mma16(acc[s], ahi, bhi);
                        }
                    }
                }
                __syncthreads();
            }

            {
                int rr = wm + (lane >> 2), cc = wn + (lane & 3) * 2;
#pragma unroll
                for (int s = 0; s < 3; s++) {
                    zz[kh * 32 + rr][cc + s * 8]         = acc[s][0];
                    zz[kh * 32 + rr][cc + s * 8 + 1]     = acc[s][1];
                    zz[kh * 32 + rr + 8][cc + s * 8]     = acc[s][2];
                    zz[kh * 32 + rr + 8][cc + s * 8 + 1] = acc[s][3];
                }
            }
            __syncthreads();
            if (stage == 0) {
#pragma unroll
                for (int i = 0; i < 6; i++) {
                    int idx = i * 512 + tid;
                    int bl = idx / 96, c = idx - bl * 96;
                    sz0[bl][c] = zz[bl][c] + zz[32 + bl][c];
                }
                __syncthreads();
            }

#pragma unroll
            for (int p = 0; p < 2; p++) {
                int idx = p * 512 + tid;
                int bl = idx >> 5, hh = idx & 31;
                int b = m0 + bl;
                float zg, zdn, zt;
                if (stage == 0) {
                    zg = sz0[bl][hh]; zdn = sz0[bl][32 + hh]; zt = sz0[bl][64 + hh];
                } else {
                    zg  = sz0[bl][hh]      + zz[bl][hh]      + zz[32 + bl][hh];
                    zdn = sz0[bl][32 + hh] + zz[bl][32 + hh] + zz[32 + bl][32 + hh];
                    zt  = sz0[bl][64 + hh] + zz[bl][64 + hh] + zz[32 + bl][64 + hh];
                }
                float gate = zg + sbase[bl][hh];
                float dyn  = zdn + sbase[bl][32 + hh];
                float tau  = softplusf(zt + sbtau[hh]);
                float hsv  = (stage == 0) ? hreg[p] : (hreg[p] + dd[p]);
                float kd   = (sigmoidf(gate) * tanhf(dyn) - hsv) / (tau + sleak[hh] + 1e-6f);
                float dt   = x_dts[b * TT + t];
                if (stage == 3) {
                    hreg[p] += dt * (rk1[p] + 3.f * rk2[p] + 3.f * rk3[p] + kd) * 0.125f;
                    g_h[b * HH + h0 + hh] = hreg[p];
                } else {
                    float dnew;
                    if (stage == 0)      { rk1[p] = kd; dnew = dt * kd * (1.f / 3.f); }
                    else if (stage == 1) { rk2[p] = kd; dnew = dt * (kd - rk1[p] * (1.f / 3.f)); }
                    else                 { rk3[p] = kd; dnew = dt * (rk1[p] - rk2[p] + kd); }
                    dd[p] = dnew;
                    float oth = __shfl_xor_sync(~0u, dnew, 1);
                    if (!(tid & 1)) {
                        uint32_t pk = pack_bf2(dnew, oth);
                        if (stage == 1) g_dB[b * 256 + ((h0 + hh) >> 1)] = pk;
                        else            g_dA[b * 256 + ((h0 + hh) >> 1)] = pk;
                    }
                }
            }
            gbar(gid);
        }
    }

    // ===== final projection =====
    {
        int b = bid * 2 + (tid >> 8);
        int lt = tid & 255;
        if (lt < OO) {
            float acc = b_fc[lt];
#pragma unroll 8
            for (int k = 0; k < HH; k++) acc += g_h[b * HH + k] * W_fc[k * OO + lt];
            out[b * OO + lt] = acc;
        }
    }
}

extern "C" void kernel_launch(void* const* d_in, const int* in_sizes, int n_in,
                              void* d_out, int out_size) {
    const float* x_states = (const float*)d_in[0];
    const float* x_dts    = (const float*)d_in[1];
    const float* Wq = (const float*)d_in[2];  const float* bq = (const float*)d_in[3];
    const float* Wk = (const float*)d_in[4];  const float* bk = (const float*)d_in[5];
    const float* Wv = (const float*)d_in[6];  const float* bv = (const float*)d_in[7];
    const float* W_gd = (const float*)d_in[8]; const float* b_gd = (const float*)d_in[9];
    const float* W_tau = (const float*)d_in[10]; const float* b_tau = (const float*)d_in[11];
    const float* gleak = (const float*)d_in[12]; const float* cm = (const float*)d_in[13];
    const float* W_fc = (const float*)d_in[14]; const float* b_fc = (const float*)d_in[15];
    float* out = (float*)d_out;

    cudaFuncSetAttribute(mega, cudaFuncAttributeMaxDynamicSharedMemorySize, SMEM_BYTES);
    mega<<<NBLK, NTHR, SMEM_BYTES>>>(x_states, x_dts, Wq, bq, Wk, bk, Wv, bv,
                                     W_gd, b_gd, W_tau, b_tau, gleak, cm,
                                     W_fc, b_fc, out);
}

// round 10
// speedup vs baseline: 1.7448x; 1.2662x over previous
#include <cuda_runtime.h>
#include <cuda_bf16.h>
#include <math.h>
#include <stdint.h>

#define BB 256
#define TT 128
#define DD 64
#define HH 512
#define AA 128
#define OO 32
#define NBLK 128
#define NTHR 512

__device__ float g_K[BB * TT * AA];
__device__ float g_V[BB * TT * AA];
__device__ uint32_t g_WBLo[16 * 96 * 256];   // stage lo residual [hg][n][kq]
__device__ uint32_t g_WKVHi[NBLK * 16 * 256]; // per-block KV weight slice hi [bid][n][kq]
__device__ uint32_t g_WKVLo[NBLK * 16 * 256];
__device__ float g_ctx[BB * AA];
__device__ float g_h[BB * HH];
__device__ uint32_t g_hHi[BB * 256];         // h packed bf16x2
__device__ uint32_t g_hLo[BB * 256];
__device__ uint32_t g_dA[BB * 256];          // packed bf16x2 deltas
__device__ uint32_t g_dB[BB * 256];
__device__ unsigned g_cnt[8];
__device__ volatile unsigned g_gen[8];

__device__ __forceinline__ float softplusf(float x) {
    return (x > 20.f) ? x : log1pf(expf(x));
}
__device__ __forceinline__ float sigmoidf(float x) {
    return 1.f / (1.f + expf(-x));
}
__device__ __forceinline__ float bfr(float x) {
    return __bfloat162float(__float2bfloat16(x));
}
__device__ __forceinline__ void mma16(float* d, const uint32_t* a, const uint32_t* b) {
    asm volatile(
        "mma.sync.aligned.m16n8k16.row.col.f32.bf16.bf16.f32 "
        "{%0,%1,%2,%3},{%4,%5,%6,%7},{%8,%9},{%0,%1,%2,%3};"
        : "+f"(d[0]), "+f"(d[1]), "+f"(d[2]), "+f"(d[3])
        : "r"(a[0]), "r"(a[1]), "r"(a[2]), "r"(a[3]), "r"(b[0]), "r"(b[1]));
}
__device__ __forceinline__ uint32_t pack_bf2(float a, float b) {
    __nv_bfloat162 t = __floats2bfloat162_rn(a, b);
    return *(uint32_t*)&t;
}
__device__ __forceinline__ uint32_t s2u(const void* p) {
    return (uint32_t)__cvta_generic_to_shared(p);
}
__device__ __forceinline__ void ldsm4(uint32_t* r, uint32_t a) {
    asm volatile("ldmatrix.sync.aligned.m8n8.x4.shared.b16 {%0,%1,%2,%3}, [%4];"
                 : "=r"(r[0]), "=r"(r[1]), "=r"(r[2]), "=r"(r[3]) : "r"(a));
}
__device__ __forceinline__ void ldsm2(uint32_t* r, uint32_t a) {
    asm volatile("ldmatrix.sync.aligned.m8n8.x2.shared.b16 {%0,%1}, [%2];"
                 : "=r"(r[0]), "=r"(r[1]) : "r"(a));
}

__device__ __forceinline__ void gbar(int idx) {
    __syncthreads();
    if (threadIdx.x == 0) {
        __threadfence();
        unsigned gen = g_gen[idx];
        if (atomicAdd(&g_cnt[idx], 1u) == 15u) {
            g_cnt[idx] = 0;
            __threadfence();
            g_gen[idx] = gen + 1;
        } else {
            while (g_gen[idx] == gen) __nanosleep(32);
            __threadfence();
        }
    }
    __syncthreads();
}

#define O_W  0
#define O_A  99840
#define O_AL 133120
#define O_Z  166400
#define O_SB 190976
#define O_SZ 199168
#define SMEM_BYTES 211456

typedef uint32_t U17[17];

__global__ void __launch_bounds__(NTHR, 1) mega(
    const float* __restrict__ x_states, const float* __restrict__ x_dts,
    const float* __restrict__ Wq, const float* __restrict__ bq,
    const float* __restrict__ Wk, const float* __restrict__ bk,
    const float* __restrict__ Wv, const float* __restrict__ bv,
    const float* __restrict__ W_gd, const float* __restrict__ b_gd,
    const float* __restrict__ W_tau, const float* __restrict__ b_tau,
    const float* __restrict__ gleak, const float* __restrict__ cm,
    const float* __restrict__ W_fc, const float* __restrict__ b_fc,
    float* __restrict__ out)
{
    extern __shared__ char smraw[];
    __shared__ float sleak[32], sbtau[32];
    uint32_t* Ws   = (uint32_t*)(smraw + O_W);
    uint32_t* AsHi = (uint32_t*)(smraw + O_A);
    uint32_t* AsLo = (uint32_t*)(smraw + O_AL);
    float (*zz)[96]    = (float(*)[96])(smraw + O_Z);
    float (*sbase)[64] = (float(*)[64])(smraw + O_SB);
    float (*sz0)[96]   = (float(*)[96])(smraw + O_SZ);
    uint32_t uW  = s2u(smraw + O_W);
    uint32_t uA  = s2u(smraw + O_A);
    uint32_t uAL = s2u(smraw + O_AL);
    uint32_t uZ  = s2u(smraw + O_Z);
    uint32_t uSB = s2u(smraw + O_SB);

    int bid = blockIdx.x, tid = threadIdx.x;
    int lane = tid & 31, wid = tid >> 5;
    int gid = bid >> 4, hg = bid & 15;
    int m0 = gid * 32, h0 = hg * 32;

    // ===== prep =====
    if (tid < 32) {
        sleak[tid] = softplusf(cm[h0 + tid]) + softplusf(gleak[h0 + tid]);
        sbtau[tid] = b_tau[h0 + tid];
    }
    for (int idx = tid; idx < 96 * 256; idx += NTHR) {
        int n = idx >> 8, kq = idx & 255, k0 = kq * 2;
        float w0, w1;
        if (n < 32)      { w0 = W_gd[(64 + k0) * 1024 + h0 + n];       w1 = W_gd[(65 + k0) * 1024 + h0 + n]; }
        else if (n < 64) { w0 = W_gd[(64 + k0) * 1024 + 512 + h0 + n - 32]; w1 = W_gd[(65 + k0) * 1024 + 512 + h0 + n - 32]; }
        else             { w0 = W_tau[k0 * 512 + h0 + n - 64];         w1 = W_tau[(k0 + 1) * 512 + h0 + n - 64]; }
        float a = bfr(w0), b = bfr(w1);
        Ws[n * 260 + kq] = pack_bf2(a, b);
        g_WBLo[(hg * 96 + n) * 256 + kq] = pack_bf2(w0 - a, w1 - b);
    }
    for (int idx = tid; idx < 16 * 256; idx += NTHR) {   // KV weight slice
        int n = idx >> 8, kq = idx & 255, k0 = kq * 2;
        int nn = hg * 16 + n, ncol = nn & 127;
        const float* W = (nn < 128) ? Wk : Wv;
        float w0 = W[k0 * 128 + ncol], w1 = W[(k0 + 1) * 128 + ncol];
        float a = bfr(w0), b = bfr(w1);
        g_WKVHi[(bid * 16 + n) * 256 + kq] = pack_bf2(a, b);
        g_WKVLo[(bid * 16 + n) * 256 + kq] = pack_bf2(w0 - a, w1 - b);
    }
    for (int idx = tid; idx < 32 * HH; idx += NTHR) g_h[m0 * HH + idx] = 0.f;
    {   // zero packed h slice (rows m0..m0+31, cols hg*16..+16)
        int mzr = tid >> 4, czc = tid & 15;
        g_hHi[(m0 + mzr) * 256 + hg * 16 + czc] = 0;
        g_hLo[(m0 + mzr) * 256 + hg * 16 + czc] = 0;
    }
    gbar(gid);

    float hreg[2] = {0.f, 0.f}, rk1[2], rk2[2], rk3[2], dd[2];
    int kh = wid >> 3, wl = wid & 7;
    int wm = (wl >> 2) * 16, wn = (wl & 3) * 24;
    int qa = lane & 3;
    // ldmatrix per-lane offsets (u32 elements)
    int aSel = (lane >> 4) << 2;
    int bSel = ((lane >> 3) & 1) << 2;
    int rowA_st = (wm + (lane & 15)) * 260 + aSel;
    int rowB0 = (wn + 0 * 8 + (lane & 7)) * 260 + bSel;
    int rowB1 = (wn + 1 * 8 + (lane & 7)) * 260 + bSel;
    int rowB2 = (wn + 2 * 8 + (lane & 7)) * 260 + bSel;
    // KV warp mapping: 2m x 2n x 4k
    int wkn = wid & 1, wkm = (wid >> 1) & 1, wks = wid >> 2;
    int rowA_kv = (wkm * 16 + (lane & 15)) * 260 + aSel;
    int rowB_kv = (wkn * 8 + (lane & 7)) * 260 + bSel;

    for (int t = 0; t < TT; t++) {
        // ---- KV (tensorized): row t-1 = h @ [Wk|Wv] slice, 32b x 16n ----
        if (t > 0) {
            // stage packed A (h hi/lo) and B (KV weights hi/lo)
#pragma unroll
            for (int i = 0; i < 4; i++) {
                int u4 = i * 512 + tid;
                int m = u4 >> 6, q4 = u4 & 63;
                *(uint4*)&AsHi[m * 260 + q4 * 4] = ((const uint4*)&g_hHi[(m0 + m) * 256])[q4];
                *(uint4*)&AsLo[m * 260 + q4 * 4] = ((const uint4*)&g_hLo[(m0 + m) * 256])[q4];
            }
            uint32_t* Bh = (uint32_t*)(smraw + O_Z);
            uint32_t* Bl = (uint32_t*)(smraw + O_SB);
#pragma unroll
            for (int i = 0; i < 2; i++) {
                int u4 = i * 512 + tid;
                int n = u4 >> 6, q4 = u4 & 63;
                *(uint4*)&Bh[n * 260 + q4 * 4] = ((const uint4*)&g_WKVHi[(bid * 16 + n) * 256])[q4];
                *(uint4*)&Bl[n * 260 + q4 * 4] = ((const uint4*)&g_WKVLo[(bid * 16 + n) * 256])[q4];
            }
            __syncthreads();
            float acc[4] = {0.f, 0.f, 0.f, 0.f};
#pragma unroll
            for (int it = 0; it < 8; it++) {
                int kq0 = wks * 64 + it * 8;
                uint32_t ahi[4], alo[4], bhi[2], blo[2];
                ldsm4(ahi, uA  + (rowA_kv + kq0) * 4);
                ldsm4(alo, uAL + (rowA_kv + kq0) * 4);
                ldsm2(bhi, uZ  + (rowB_kv + kq0) * 4);
                ldsm2(blo, uSB + (rowB_kv + kq0) * 4);
                mma16(acc, ahi, bhi);
                mma16(acc, alo, bhi);
                mma16(acc, ahi, blo);
            }
            __syncthreads();
            float* pkv = (float*)(smraw + O_AL);
            {
                int ml = wkm * 16 + (lane >> 2), nl = wkn * 8 + (lane & 3) * 2;
                int off = wks * 512 + ml * 16 + nl;
                pkv[off] = acc[0]; pkv[off + 1] = acc[1];
                pkv[off + 128] = acc[2]; pkv[off + 129] = acc[3];
            }
            __syncthreads();
            {
                int m = tid >> 4, n = tid & 15;
                float s = pkv[m * 16 + n] + pkv[512 + m * 16 + n] +
                          pkv[1024 + m * 16 + n] + pkv[1536 + m * 16 + n];
                int nn = hg * 16 + n, ncol = nn & 127;
                s += (nn < 128) ? bk[ncol] : bv[ncol];
                float* dst = (nn < 128) ? g_K : g_V;
                dst[((m0 + m) * TT + (t - 1)) * AA + ncol] = s;
            }
            gbar(gid);
        }

        // ---- ATTN: 2 batches per block (unchanged) ----
        {
            float* aq   = (float*)(smraw + O_A);
            float* asc  = aq + 256;
            float* actx = asc + 256;
            float* axs  = actx + 512;
            float* ared = axs + 128;
            int hB = tid >> 8, lt = tid & 255;
            int b = bid * 2 + hB;
            if (t == 0) {
                if (lt < 128) g_ctx[b * AA + lt] = 0.f;
            } else {
                if (lt < DD) axs[hB * 64 + lt] = x_states[(b * TT + t) * DD + lt];
                __syncthreads();
                if (lt < 128) {
                    float qv = bq[lt];
#pragma unroll 16
                    for (int d = 0; d < DD; d++) qv += axs[hB * 64 + d] * Wq[d * AA + lt];
                    aq[hB * 128 + lt] = qv;
                }
                __syncthreads();
                float s = -1e30f;
                if (lt < t) {
                    const float4* Kp = (const float4*)&g_K[(b * TT + lt) * AA];
                    const float* qh = &aq[hB * 128];
                    float dot = 0.f;
#pragma unroll 8
                    for (int a4 = 0; a4 < AA / 4; a4++) {
                        float4 kv = Kp[a4];
                        dot += kv.x * qh[4 * a4] + kv.y * qh[4 * a4 + 1] +
                               kv.z * qh[4 * a4 + 2] + kv.w * qh[4 * a4 + 3];
                    }
                    s = dot * (1.f / 11.313708498984761f);
                }
                float m = s;
#pragma unroll
                for (int o = 16; o > 0; o >>= 1) m = fmaxf(m, __shfl_xor_sync(~0u, m, o));
                if (lane == 0) ared[hB * 8 + (wid & 7)] = m;
                __syncthreads();
                m = ared[hB * 8];
#pragma unroll
                for (int i = 1; i < 8; i++) m = fmaxf(m, ared[hB * 8 + i]);
                float e = (lt < t) ? expf(s - m) : 0.f;
                float su = e;
#pragma unroll
                for (int o = 16; o > 0; o >>= 1) su += __shfl_xor_sync(~0u, su, o);
                __syncthreads();
                if (lane == 0) ared[hB * 8 + (wid & 7)] = su;
                __syncthreads();
                su = 0.f;
#pragma unroll
                for (int i = 0; i < 8; i++) su += ared[hB * 8 + i];
                if (lt < 128) asc[hB * 128 + lt] = (lt < t) ? (e / su) : 0.f;
                __syncthreads();
                {
                    int a = lt & 127, th = lt >> 7;
                    int tlim = (t + 7) & ~7;
                    float c = 0.f;
#pragma unroll 8
                    for (int sx = th; sx < tlim; sx += 2)
                        c += asc[hB * 128 + sx] * g_V[(b * TT + sx) * AA + a];
                    actx[(hB * 2 + th) * 128 + a] = c;
                }
                __syncthreads();
                if (lt < 128)
                    g_ctx[b * AA + lt] = actx[hB * 256 + lt] + actx[hB * 256 + 128 + lt];
            }
            gbar(gid);
        }

        // ---- 4 RK stages ----
        for (int stage = 0; stage < 4; stage++) {
            float acc[3][4];
#pragma unroll
            for (int s = 0; s < 3; s++)
#pragma unroll
                for (int i = 0; i < 4; i++) acc[s][i] = 0.f;

            if (stage == 0) {
                float (*cz)[192] = (float(*)[192])(smraw + O_Z);
#pragma unroll
                for (int i = 0; i < 12; i++) {
                    int idx = i * 512 + tid;
                    int bl = idx / 192, k = idx - bl * 192;
                    cz[bl][k] = (k < 64) ? x_states[((m0 + bl) * TT + t) * DD + k]
                                         : g_ctx[(m0 + bl) * AA + (k - 64)];
                }
#pragma unroll
                for (int i = 0; i < 4; i++) {       // A = packed h hi/lo
                    int u4 = i * 512 + tid;
                    int m = u4 >> 6, q4 = u4 & 63;
                    *(uint4*)&AsHi[m * 260 + q4 * 4] = ((const uint4*)&g_hHi[(m0 + m) * 256])[q4];
                    *(uint4*)&AsLo[m * 260 + q4 * 4] = ((const uint4*)&g_hLo[(m0 + m) * 256])[q4];
                }
                __syncthreads();
                {   // base GEMM -> sbase
                    int tx2 = tid & 63, ty2 = tid >> 6;
                    int col = (tx2 < 32) ? (h0 + tx2) : (512 + h0 + tx2 - 32);
                    float a0 = 0, a1 = 0, a2 = 0, a3 = 0;
#pragma unroll 8
                    for (int k = 0; k < 64; k++) {
                        float w = W_gd[k * 1024 + col];
                        a0 += cz[ty2 * 4 + 0][k] * w; a1 += cz[ty2 * 4 + 1][k] * w;
                        a2 += cz[ty2 * 4 + 2][k] * w; a3 += cz[ty2 * 4 + 3][k] * w;
                    }
#pragma unroll 8
                    for (int k = 64; k < 192; k++) {
                        float w = W_gd[(k + 512) * 1024 + col];
                        a0 += cz[ty2 * 4 + 0][k] * w; a1 += cz[ty2 * 4 + 1][k] * w;
                        a2 += cz[ty2 * 4 + 2][k] * w; a3 += cz[ty2 * 4 + 3][k] * w;
                    }
                    float bg = b_gd[col];
                    sbase[ty2 * 4 + 0][tx2] = a0 + bg; sbase[ty2 * 4 + 1][tx2] = a1 + bg;
                    sbase[ty2 * 4 + 2][tx2] = a2 + bg; sbase[ty2 * 4 + 3][tx2] = a3 + bg;
                }
                __syncthreads();
                // hi pass via ldmatrix: (ahi+alo) * bhi
#pragma unroll
                for (int it = 0; it < 8; it++) {
#pragma unroll
                    for (int kb2 = 0; kb2 < 16; kb2 += 8) {
                        int kq0 = kh * 128 + it * 16 + kb2;
                        uint32_t ahi[4], alo[4], bw[2];
                        ldsm4(ahi, uA  + (rowA_st + kq0) * 4);
                        ldsm4(alo, uAL + (rowA_st + kq0) * 4);
                        ldsm2(bw, uW + (rowB0 + kq0) * 4);
                        mma16(acc[0], ahi, bw); mma16(acc[0], alo, bw);
                        ldsm2(bw, uW + (rowB1 + kq0) * 4);
                        mma16(acc[1], ahi, bw); mma16(acc[1], alo, bw);
                        ldsm2(bw, uW + (rowB2 + kq0) * 4);
                        mma16(acc[2], ahi, bw); mma16(acc[2], alo, bw);
                    }
                }
                // lo pass: ahi * blo (B chunk-staged, scalar LDS — unchanged)
                U17* BsLo = (U17*)(smraw + O_Z);
                int r = wm + (lane >> 2);
                __syncthreads();
                for (int it = 0; it < 8; it++) {
#pragma unroll
                    for (int i = 0; i < 6; i++) {
                        int idx = i * 512 + tid;
                        int n192 = idx >> 4, kq = idx & 15;
                        int khh = (n192 >= 96), n = n192 - khh * 96;
                        BsLo[n192][kq] = g_WBLo[(hg * 96 + n) * 256 + khh * 128 + it * 16 + kq];
                    }
                    __syncthreads();
                    int kq0 = kh * 128 + it * 16;
#pragma unroll
                    for (int kb2 = 0; kb2 < 16; kb2 += 8) {
                        uint32_t ahi[4];
                        ahi[0] = AsHi[r * 260 + kq0 + kb2 + qa];
                        ahi[1] = AsHi[(r + 8) * 260 + kq0 + kb2 + qa];
                        ahi[2] = AsHi[r * 260 + kq0 + kb2 + 4 + qa];
                        ahi[3] = AsHi[(r + 8) * 260 + kq0 + kb2 + 4 + qa];
#pragma unroll
                        for (int s = 0; s < 3; s++) {
                            int n = wn + s * 8 + (lane >> 2);
                            uint32_t blo[2];
                            blo[0] = BsLo[kh * 96 + n][kb2 + qa];
                            blo[1] = BsLo[kh * 96 + n][kb2 + 4 + qa];
                            mma16(acc[s], ahi, blo);
                        }
                    }
                    __syncthreads();
                }
            } else {
                const uint32_t* Dg = (stage == 2) ? g_dB : g_dA;
#pragma unroll
                for (int i = 0; i < 4; i++) {
                    int idx = i * 512 + tid;
                    int m = idx >> 6, q4 = idx & 63;
                    *(uint4*)&AsHi[m * 260 + q4 * 4] = ((const uint4*)&Dg[(m0 + m) * 256])[q4];
                }
                __syncthreads();
#pragma unroll
                for (int it = 0; it < 8; it++) {
#pragma unroll
                    for (int kb2 = 0; kb2 < 16; kb2 += 8) {
                        int kq0 = kh * 128 + it * 16 + kb2;
                        uint32_t ahi[4], bw[2];
                        ldsm4(ahi, uA + (rowA_st + kq0) * 4);
                        ldsm2(bw, uW + (rowB0 + kq0) * 4);
                        mma16(acc[0], ahi, bw);
                        ldsm2(bw, uW + (rowB1 + kq0) * 4);
                        mma16(acc[1], ahi, bw);
                        ldsm2(bw, uW + (rowB2 + kq0) * 4);
                        mma16(acc[2], ahi, bw);
                    }
                }
                __syncthreads();
            }

            {
                int rr = wm + (lane >> 2), cc = wn + (lane & 3) * 2;
#pragma unroll
                for (int s = 0; s < 3; s++) {
                    zz[kh * 32 + rr][cc + s * 8]         = acc[s][0];
                    zz[kh * 32 + rr][cc + s * 8 + 1]     = acc[s][1];
                    zz[kh * 32 + rr + 8][cc + s * 8]     = acc[s][2];
                    zz[kh * 32 + rr + 8][cc + s * 8 + 1] = acc[s][3];
                }
            }
            __syncthreads();
            if (stage == 0) {
#pragma unroll
                for (int i = 0; i < 6; i++) {
                    int idx = i * 512 + tid;
                    int bl = idx / 96, c = idx - bl * 96;
                    sz0[bl][c] = zz[bl][c] + zz[32 + bl][c];
                }
                __syncthreads();
            }

#pragma unroll
            for (int p = 0; p < 2; p++) {
                int idx = p * 512 + tid;
                int bl = idx >> 5, hh = idx & 31;
                int b = m0 + bl;
                float zg, zdn, zt;
                if (stage == 0) {
                    zg = sz0[bl][hh]; zdn = sz0[bl][32 + hh]; zt = sz0[bl][64 + hh];
                } else {
                    zg  = sz0[bl][hh]      + zz[bl][hh]      + zz[32 + bl][hh];
                    zdn = sz0[bl][32 + hh] + zz[bl][32 + hh] + zz[32 + bl][32 + hh];
                    zt  = sz0[bl][64 + hh] + zz[bl][64 + hh] + zz[32 + bl][64 + hh];
                }
                float gate = zg + sbase[bl][hh];
                float dyn  = zdn + sbase[bl][32 + hh];
                float tau  = softplusf(zt + sbtau[hh]);
                float hsv  = (stage == 0) ? hreg[p] : (hreg[p] + dd[p]);
                float kd   = (sigmoidf(gate) * tanhf(dyn) - hsv) / (tau + sleak[hh] + 1e-6f);
                float dt   = x_dts[b * TT + t];
                if (stage == 3) {
                    hreg[p] += dt * (rk1[p] + 3.f * rk2[p] + 3.f * rk3[p] + kd) * 0.125f;
                    g_h[b * HH + h0 + hh] = hreg[p];
                    float hi = bfr(hreg[p]);
                    float lo = hreg[p] - hi;
                    float ohi = __shfl_xor_sync(~0u, hi, 1);
                    float olo = __shfl_xor_sync(~0u, lo, 1);
                    if (!(tid & 1)) {
                        g_hHi[b * 256 + ((h0 + hh) >> 1)] = pack_bf2(hi, ohi);
                        g_hLo[b * 256 + ((h0 + hh) >> 1)] = pack_bf2(lo, olo);
                    }
                } else {
                    float dnew;
                    if (stage == 0)      { rk1[p] = kd; dnew = dt * kd * (1.f / 3.f); }
                    else if (stage == 1) { rk2[p] = kd; dnew = dt * (kd - rk1[p] * (1.f / 3.f)); }
                    else                 { rk3[p] = kd; dnew = dt * (rk1[p] - rk2[p] + kd); }
                    dd[p] = dnew;
                    float oth = __shfl_xor_sync(~0u, dnew, 1);
                    if (!(tid & 1)) {
                        uint32_t pk = pack_bf2(dnew, oth);
                        if (stage == 1) g_dB[b * 256 + ((h0 + hh) >> 1)] = pk;
                        else            g_dA[b * 256 + ((h0 + hh) >> 1)] = pk;
                    }
                }
            }
            gbar(gid);
        }
    }

    // ===== final projection =====
    {
        int b = bid * 2 + (tid >> 8);
        int lt = tid & 255;
        if (lt < OO) {
            float acc = b_fc[lt];
#pragma unroll 8
            for (int k = 0; k < HH; k++) acc += g_h[b * HH + k] * W_fc[k * OO + lt];
            out[b * OO + lt] = acc;
        }
    }
}

extern "C" void kernel_launch(void* const* d_in, const int* in_sizes, int n_in,
                              void* d_out, int out_size) {
    const float* x_states = (const float*)d_in[0];
    const float* x_dts    = (const float*)d_in[1];
    const float* Wq = (const float*)d_in[2];  const float* bq = (const float*)d_in[3];
    const float* Wk = (const float*)d_in[4];  const float* bk = (const float*)d_in[5];
    const float* Wv = (const float*)d_in[6];  const float* bv = (const float*)d_in[7];
    const float* W_gd = (const float*)d_in[8]; const float* b_gd = (const float*)d_in[9];
    const float* W_tau = (const float*)d_in[10]; const float* b_tau = (const float*)d_in[11];
    const float* gleak = (const float*)d_in[12]; const float* cm = (const float*)d_in[13];
    const float* W_fc = (const float*)d_in[14]; const float* b_fc = (const float*)d_in[15];
    float* out = (float*)d_out;

    cudaFuncSetAttribute(mega, cudaFuncAttributeMaxDynamicSharedMemorySize, SMEM_BYTES);
    mega<<<NBLK, NTHR, SMEM_BYTES>>>(x_states, x_dts, Wq, bq, Wk, bk, Wv, bv,
                                     W_gd, b_gd, W_tau, b_tau, gleak, cm,
                                     W_fc, b_fc, out);
}

// round 11
// speedup vs baseline: 1.7896x; 1.0257x over previous
#include <cuda_runtime.h>
#include <cuda_bf16.h>
#include <math.h>
#include <stdint.h>

#define BB 256
#define TT 128
#define DD 64
#define HH 512
#define AA 128
#define OO 32
#define NBLK 128
#define NTHR 512

__device__ float g_K[BB * TT * AA];
__device__ float g_V[BB * TT * AA];
__device__ uint32_t g_WBLo[16 * 96 * 256];    // stage lo residual [hg][n][kq]
__device__ uint32_t g_WKVHi[NBLK * 16 * 256]; // per-block KV weight slice
__device__ uint32_t g_WKVLo[NBLK * 16 * 256];
__device__ uint32_t g_WBaseHi[NBLK * 64 * 96]; // per-block base W slice [bid][n][kq]
__device__ uint32_t g_WBaseLo[NBLK * 64 * 96];
__device__ float g_ctx[BB * AA];
__device__ float g_h[BB * HH];
__device__ uint32_t g_hHi[BB * 256];
__device__ uint32_t g_hLo[BB * 256];
__device__ uint32_t g_dA[BB * 256];
__device__ uint32_t g_dB[BB * 256];
__device__ unsigned g_cnt[8];
__device__ volatile unsigned g_gen[8];

__device__ __forceinline__ float softplusf(float x) {
    return (x > 20.f) ? x : log1pf(expf(x));
}
__device__ __forceinline__ float sigmoidf(float x) {
    return 1.f / (1.f + expf(-x));
}
__device__ __forceinline__ float bfr(float x) {
    return __bfloat162float(__float2bfloat16(x));
}
__device__ __forceinline__ void mma16(float* d, const uint32_t* a, const uint32_t* b) {
    asm volatile(
        "mma.sync.aligned.m16n8k16.row.col.f32.bf16.bf16.f32 "
        "{%0,%1,%2,%3},{%4,%5,%6,%7},{%8,%9},{%0,%1,%2,%3};"
        : "+f"(d[0]), "+f"(d[1]), "+f"(d[2]), "+f"(d[3])
        : "r"(a[0]), "r"(a[1]), "r"(a[2]), "r"(a[3]), "r"(b[0]), "r"(b[1]));
}
__device__ __forceinline__ uint32_t pack_bf2(float a, float b) {
    __nv_bfloat162 t = __floats2bfloat162_rn(a, b);
    return *(uint32_t*)&t;
}
__device__ __forceinline__ uint32_t s2u(const void* p) {
    return (uint32_t)__cvta_generic_to_shared(p);
}
__device__ __forceinline__ void ldsm4(uint32_t* r, uint32_t a) {
    asm volatile("ldmatrix.sync.aligned.m8n8.x4.shared.b16 {%0,%1,%2,%3}, [%4];"
                 : "=r"(r[0]), "=r"(r[1]), "=r"(r[2]), "=r"(r[3]) : "r"(a));
}
__device__ __forceinline__ void ldsm2(uint32_t* r, uint32_t a) {
    asm volatile("ldmatrix.sync.aligned.m8n8.x2.shared.b16 {%0,%1}, [%2];"
                 : "=r"(r[0]), "=r"(r[1]) : "r"(a));
}

__device__ __forceinline__ void gbar(int idx) {
    __syncthreads();
    if (threadIdx.x == 0) {
        __threadfence();
        unsigned gen = g_gen[idx];
        if (atomicAdd(&g_cnt[idx], 1u) == 15u) {
            g_cnt[idx] = 0;
            __threadfence();
            g_gen[idx] = gen + 1;
        } else {
            while (g_gen[idx] == gen) __nanosleep(32);
            __threadfence();
        }
    }
    __syncthreads();
}

#define O_W  0
#define O_A  99840
#define O_AL 133120
#define O_Z  166400
#define O_SB 190976
#define O_SZ 199168
#define SMEM_BYTES 211456

__global__ void __launch_bounds__(NTHR, 1) mega(
    const float* __restrict__ x_states, const float* __restrict__ x_dts,
    const float* __restrict__ Wq, const float* __restrict__ bq,
    const float* __restrict__ Wk, const float* __restrict__ bk,
    const float* __restrict__ Wv, const float* __restrict__ bv,
    const float* __restrict__ W_gd, const float* __restrict__ b_gd,
    const float* __restrict__ W_tau, const float* __restrict__ b_tau,
    const float* __restrict__ gleak, const float* __restrict__ cm,
    const float* __restrict__ W_fc, const float* __restrict__ b_fc,
    float* __restrict__ out)
{
    extern __shared__ char smraw[];
    __shared__ float sleak[32], sbtau[32];
    uint32_t* Ws   = (uint32_t*)(smraw + O_W);
    uint32_t* AsHi = (uint32_t*)(smraw + O_A);
    uint32_t* AsLo = (uint32_t*)(smraw + O_AL);
    float (*zz)[96]    = (float(*)[96])(smraw + O_Z);
    float (*sbase)[64] = (float(*)[64])(smraw + O_SB);
    float (*sz0)[96]   = (float(*)[96])(smraw + O_SZ);
    uint32_t uW  = s2u(smraw + O_W);
    uint32_t uA  = s2u(smraw + O_A);
    uint32_t uAL = s2u(smraw + O_AL);
    uint32_t uZ  = s2u(smraw + O_Z);
    uint32_t uSB = s2u(smraw + O_SB);

    int bid = blockIdx.x, tid = threadIdx.x;
    int lane = tid & 31, wid = tid >> 5;
    int gid = bid >> 4, hg = bid & 15;
    int m0 = gid * 32, h0 = hg * 32;

    // ===== prep =====
    if (tid < 32) {
        sleak[tid] = softplusf(cm[h0 + tid]) + softplusf(gleak[h0 + tid]);
        sbtau[tid] = b_tau[h0 + tid];
    }
    for (int idx = tid; idx < 96 * 256; idx += NTHR) {
        int n = idx >> 8, kq = idx & 255, k0 = kq * 2;
        float w0, w1;
        if (n < 32)      { w0 = W_gd[(64 + k0) * 1024 + h0 + n];       w1 = W_gd[(65 + k0) * 1024 + h0 + n]; }
        else if (n < 64) { w0 = W_gd[(64 + k0) * 1024 + 512 + h0 + n - 32]; w1 = W_gd[(65 + k0) * 1024 + 512 + h0 + n - 32]; }
        else             { w0 = W_tau[k0 * 512 + h0 + n - 64];         w1 = W_tau[(k0 + 1) * 512 + h0 + n - 64]; }
        float a = bfr(w0), b = bfr(w1);
        Ws[n * 260 + kq] = pack_bf2(a, b);
        g_WBLo[(hg * 96 + n) * 256 + kq] = pack_bf2(w0 - a, w1 - b);
    }
    for (int idx = tid; idx < 16 * 256; idx += NTHR) {   // KV weight slice
        int n = idx >> 8, kq = idx & 255, k0 = kq * 2;
        int nn = hg * 16 + n, ncol = nn & 127;
        const float* W = (nn < 128) ? Wk : Wv;
        float w0 = W[k0 * 128 + ncol], w1 = W[(k0 + 1) * 128 + ncol];
        float a = bfr(w0), b = bfr(w1);
        g_WKVHi[(bid * 16 + n) * 256 + kq] = pack_bf2(a, b);
        g_WKVLo[(bid * 16 + n) * 256 + kq] = pack_bf2(w0 - a, w1 - b);
    }
    for (int idx = tid; idx < 64 * 96; idx += NTHR) {    // base weight slice
        int n = idx / 96, kq = idx - n * 96, k0 = kq * 2;
        int row0 = (k0 < 64) ? k0 : (k0 + 512);
        int col = (n < 32) ? (h0 + n) : (512 + h0 + n - 32);
        float w0 = W_gd[row0 * 1024 + col], w1 = W_gd[(row0 + 1) * 1024 + col];
        float a = bfr(w0), b = bfr(w1);
        g_WBaseHi[(bid * 64 + n) * 96 + kq] = pack_bf2(a, b);
        g_WBaseLo[(bid * 64 + n) * 96 + kq] = pack_bf2(w0 - a, w1 - b);
    }
    for (int idx = tid; idx < 32 * HH; idx += NTHR) g_h[m0 * HH + idx] = 0.f;
    {
        int mzr = tid >> 4, czc = tid & 15;
        g_hHi[(m0 + mzr) * 256 + hg * 16 + czc] = 0;
        g_hLo[(m0 + mzr) * 256 + hg * 16 + czc] = 0;
    }
    gbar(gid);

    float hreg[2] = {0.f, 0.f}, rk1[2], rk2[2], rk3[2], dd[2];
    int kh = wid >> 3, wl = wid & 7;
    int wm = (wl >> 2) * 16, wn = (wl & 3) * 24;
    int qa = lane & 3;
    int aSel = (lane >> 4) << 2;
    int bSel = ((lane >> 3) & 1) << 2;
    int rowA_st = (wm + (lane & 15)) * 260 + aSel;
    int rowB0 = (wn + 0 * 8 + (lane & 7)) * 260 + bSel;
    int rowB1 = (wn + 1 * 8 + (lane & 7)) * 260 + bSel;
    int rowB2 = (wn + 2 * 8 + (lane & 7)) * 260 + bSel;
    // lo-residual direct-LDG bases per n-subtile
    long loN0 = (long)(hg * 96 + wn + 0 * 8 + (lane >> 2)) * 256 + qa;
    long loN1 = (long)(hg * 96 + wn + 1 * 8 + (lane >> 2)) * 256 + qa;
    long loN2 = (long)(hg * 96 + wn + 2 * 8 + (lane >> 2)) * 256 + qa;
    // KV warp mapping
    int wkn = wid & 1, wkm = (wid >> 1) & 1, wks = wid >> 2;
    int rowA_kv = (wkm * 16 + (lane & 15)) * 260 + aSel;
    int rowB_kv = (wkn * 8 + (lane & 7)) * 260 + bSel;
    // base warp mapping: 2m x 2n x 4k
    int wbk = wid >> 2, wbm = (wid >> 1) & 1, wbn = wid & 1;
    int rowA_bs = (wbm * 16 + (lane & 15)) * 260 + aSel;

    for (int t = 0; t < TT; t++) {
        // ---- KV (tensorized): row t-1 ----
        if (t > 0) {
#pragma unroll
            for (int i = 0; i < 4; i++) {
                int u4 = i * 512 + tid;
                int m = u4 >> 6, q4 = u4 & 63;
                *(uint4*)&AsHi[m * 260 + q4 * 4] = ((const uint4*)&g_hHi[(m0 + m) * 256])[q4];
                *(uint4*)&AsLo[m * 260 + q4 * 4] = ((const uint4*)&g_hLo[(m0 + m) * 256])[q4];
            }
            uint32_t* Bh = (uint32_t*)(smraw + O_Z);
            uint32_t* Bl = (uint32_t*)(smraw + O_SB);
#pragma unroll
            for (int i = 0; i < 2; i++) {
                int u4 = i * 512 + tid;
                int n = u4 >> 6, q4 = u4 & 63;
                *(uint4*)&Bh[n * 260 + q4 * 4] = ((const uint4*)&g_WKVHi[(bid * 16 + n) * 256])[q4];
                *(uint4*)&Bl[n * 260 + q4 * 4] = ((const uint4*)&g_WKVLo[(bid * 16 + n) * 256])[q4];
            }
            __syncthreads();
            float acc[4] = {0.f, 0.f, 0.f, 0.f};
#pragma unroll
            for (int it = 0; it < 8; it++) {
                int kq0 = wks * 64 + it * 8;
                uint32_t ahi[4], alo[4], bhi[2], blo[2];
                ldsm4(ahi, uA  + (rowA_kv + kq0) * 4);
                ldsm4(alo, uAL + (rowA_kv + kq0) * 4);
                ldsm2(bhi, uZ  + (rowB_kv + kq0) * 4);
                ldsm2(blo, uSB + (rowB_kv + kq0) * 4);
                mma16(acc, ahi, bhi);
                mma16(acc, alo, bhi);
                mma16(acc, ahi, blo);
            }
            __syncthreads();
            float* pkv = (float*)(smraw + O_AL);
            {
                int ml = wkm * 16 + (lane >> 2), nl = wkn * 8 + (lane & 3) * 2;
                int off = wks * 512 + ml * 16 + nl;
                pkv[off] = acc[0]; pkv[off + 1] = acc[1];
                pkv[off + 128] = acc[2]; pkv[off + 129] = acc[3];
            }
            __syncthreads();
            {
                int m = tid >> 4, n = tid & 15;
                float s = pkv[m * 16 + n] + pkv[512 + m * 16 + n] +
                          pkv[1024 + m * 16 + n] + pkv[1536 + m * 16 + n];
                int nn = hg * 16 + n, ncol = nn & 127;
                s += (nn < 128) ? bk[ncol] : bv[ncol];
                float* dst = (nn < 128) ? g_K : g_V;
                dst[((m0 + m) * TT + (t - 1)) * AA + ncol] = s;
            }
            gbar(gid);
        }

        // ---- ATTN ----
        {
            float* aq   = (float*)(smraw + O_A);
            float* asc  = aq + 256;
            float* actx = asc + 256;
            float* axs  = actx + 512;
            float* ared = axs + 128;
            int hB = tid >> 8, lt = tid & 255;
            int b = bid * 2 + hB;
            if (t == 0) {
                if (lt < 128) g_ctx[b * AA + lt] = 0.f;
            } else {
                if (lt < DD) axs[hB * 64 + lt] = x_states[(b * TT + t) * DD + lt];
                __syncthreads();
                if (lt < 128) {
                    float qv = bq[lt];
#pragma unroll 16
                    for (int d = 0; d < DD; d++) qv += axs[hB * 64 + d] * Wq[d * AA + lt];
                    aq[hB * 128 + lt] = qv;
                }
                __syncthreads();
                float s = -1e30f;
                if (lt < t) {
                    const float4* Kp = (const float4*)&g_K[(b * TT + lt) * AA];
                    const float* qh = &aq[hB * 128];
                    float dot = 0.f;
#pragma unroll 8
                    for (int a4 = 0; a4 < AA / 4; a4++) {
                        float4 kv = Kp[a4];
                        dot += kv.x * qh[4 * a4] + kv.y * qh[4 * a4 + 1] +
                               kv.z * qh[4 * a4 + 2] + kv.w * qh[4 * a4 + 3];
                    }
                    s = dot * (1.f / 11.313708498984761f);
                }
                float m = s;
#pragma unroll
                for (int o = 16; o > 0; o >>= 1) m = fmaxf(m, __shfl_xor_sync(~0u, m, o));
                if (lane == 0) ared[hB * 8 + (wid & 7)] = m;
                __syncthreads();
                m = ared[hB * 8];
#pragma unroll
                for (int i = 1; i < 8; i++) m = fmaxf(m, ared[hB * 8 + i]);
                float e = (lt < t) ? expf(s - m) : 0.f;
                float su = e;
#pragma unroll
                for (int o = 16; o > 0; o >>= 1) su += __shfl_xor_sync(~0u, su, o);
                __syncthreads();
                if (lane == 0) ared[hB * 8 + (wid & 7)] = su;
                __syncthreads();
                su = 0.f;
#pragma unroll
                for (int i = 0; i < 8; i++) su += ared[hB * 8 + i];
                if (lt < 128) asc[hB * 128 + lt] = (lt < t) ? (e / su) : 0.f;
                __syncthreads();
                {
                    int a = lt & 127, th = lt >> 7;
                    int tlim = (t + 7) & ~7;
                    float c = 0.f;
#pragma unroll 8
                    for (int sx = th; sx < tlim; sx += 2)
                        c += asc[hB * 128 + sx] * g_V[(b * TT + sx) * AA + a];
                    actx[(hB * 2 + th) * 128 + a] = c;
                }
                __syncthreads();
                if (lt < 128)
                    g_ctx[b * AA + lt] = actx[hB * 256 + lt] + actx[hB * 256 + 128 + lt];
            }
            gbar(gid);
        }

        // ---- 4 RK stages ----
        for (int stage = 0; stage < 4; stage++) {
            float acc[3][4];
#pragma unroll
            for (int s = 0; s < 3; s++)
#pragma unroll
                for (int i = 0; i < 4; i++) acc[s][i] = 0.f;

            if (stage == 0) {
                // --- base GEMM (tensorized, 3-term, B via direct LDG) ---
#pragma unroll
                for (int i = 0; i < 6; i++) {          // A = [x|ctx] packed hi/lo
                    int idx = i * 512 + tid;           // < 3072
                    int m = idx / 96, kq = idx - m * 96;
                    int k0 = kq * 2;
                    float a0, a1;
                    if (kq < 32) {
                        const float* xr = &x_states[((m0 + m) * TT + t) * DD];
                        a0 = xr[k0]; a1 = xr[k0 + 1];
                    } else {
                        const float* cr = &g_ctx[(m0 + m) * AA];
                        a0 = cr[k0 - 64]; a1 = cr[k0 - 63];
                    }
                    float h0v = bfr(a0), h1v = bfr(a1);
                    AsHi[m * 260 + kq] = pack_bf2(h0v, h1v);
                    AsLo[m * 260 + kq] = pack_bf2(a0 - h0v, a1 - h1v);
                }
                __syncthreads();
                {
                    float accb[4][4];
#pragma unroll
                    for (int s = 0; s < 4; s++)
#pragma unroll
                        for (int i = 0; i < 4; i++) accb[s][i] = 0.f;
#pragma unroll
                    for (int ks = 0; ks < 3; ks++) {
                        int kq0 = wbk * 24 + ks * 8;
                        uint32_t ahi[4], alo[4];
                        ldsm4(ahi, uA  + (rowA_bs + kq0) * 4);
                        ldsm4(alo, uAL + (rowA_bs + kq0) * 4);
#pragma unroll
                        for (int s = 0; s < 4; s++) {
                            int nrow = wbn * 32 + s * 8 + (lane >> 2);
                            long bix = (long)(bid * 64 + nrow) * 96 + kq0 + qa;
                            uint32_t bhi[2], blo[2];
                            bhi[0] = g_WBaseHi[bix]; bhi[1] = g_WBaseHi[bix + 4];
                            blo[0] = g_WBaseLo[bix]; blo[1] = g_WBaseLo[bix + 4];
                            mma16(accb[s], ahi, bhi);
                            mma16(accb[s], alo, bhi);
                            mma16(accb[s], ahi, blo);
                        }
                    }
                    __syncthreads();
                    float* pb = (float*)(smraw + O_AL);
#pragma unroll
                    for (int s = 0; s < 4; s++) {
                        int off = wbk * 2048 + (wbm * 16 + (lane >> 2)) * 64 +
                                  wbn * 32 + s * 8 + (lane & 3) * 2;
                        pb[off] = accb[s][0]; pb[off + 1] = accb[s][1];
                        pb[off + 512] = accb[s][2]; pb[off + 513] = accb[s][3];
                    }
                    __syncthreads();
#pragma unroll
                    for (int i = 0; i < 4; i++) {
                        int idx = i * 512 + tid;       // < 2048
                        int m = idx >> 6, n = idx & 63;
                        int col = (n < 32) ? (h0 + n) : (512 + h0 + n - 32);
                        sbase[m][n] = pb[m * 64 + n] + pb[2048 + m * 64 + n] +
                                      pb[4096 + m * 64 + n] + pb[6144 + m * 64 + n] +
                                      b_gd[col];
                    }
                }
                __syncthreads();
                // --- stage A = packed h hi/lo ---
#pragma unroll
                for (int i = 0; i < 4; i++) {
                    int u4 = i * 512 + tid;
                    int m = u4 >> 6, q4 = u4 & 63;
                    *(uint4*)&AsHi[m * 260 + q4 * 4] = ((const uint4*)&g_hHi[(m0 + m) * 256])[q4];
                    *(uint4*)&AsLo[m * 260 + q4 * 4] = ((const uint4*)&g_hLo[(m0 + m) * 256])[q4];
                }
                __syncthreads();
                // --- combined 3-term pass: (ahi+alo)@Whi + ahi@Wlo(LDG) ---
#pragma unroll
                for (int it = 0; it < 8; it++) {
#pragma unroll
                    for (int kb2 = 0; kb2 < 16; kb2 += 8) {
                        int kq0 = kh * 128 + it * 16 + kb2;
                        uint32_t ahi[4], alo[4], bw[2], bl[2];
                        ldsm4(ahi, uA  + (rowA_st + kq0) * 4);
                        ldsm4(alo, uAL + (rowA_st + kq0) * 4);
                        ldsm2(bw, uW + (rowB0 + kq0) * 4);
                        bl[0] = g_WBLo[loN0 + kq0]; bl[1] = g_WBLo[loN0 + kq0 + 4];
                        mma16(acc[0], ahi, bw); mma16(acc[0], alo, bw); mma16(acc[0], ahi, bl);
                        ldsm2(bw, uW + (rowB1 + kq0) * 4);
                        bl[0] = g_WBLo[loN1 + kq0]; bl[1] = g_WBLo[loN1 + kq0 + 4];
                        mma16(acc[1], ahi, bw); mma16(acc[1], alo, bw); mma16(acc[1], ahi, bl);
                        ldsm2(bw, uW + (rowB2 + kq0) * 4);
                        bl[0] = g_WBLo[loN2 + kq0]; bl[1] = g_WBLo[loN2 + kq0 + 4];
                        mma16(acc[2], ahi, bw); mma16(acc[2], alo, bw); mma16(acc[2], ahi, bl);
                    }
                }
                __syncthreads();
            } else {
                const uint32_t* Dg = (stage == 2) ? g_dB : g_dA;
#pragma unroll
                for (int i = 0; i < 4; i++) {
                    int idx = i * 512 + tid;
                    int m = idx >> 6, q4 = idx & 63;
                    *(uint4*)&AsHi[m * 260 + q4 * 4] = ((const uint4*)&Dg[(m0 + m) * 256])[q4];
                }
                __syncthreads();
#pragma unroll
                for (int it = 0; it < 8; it++) {
#pragma unroll
                    for (int kb2 = 0; kb2 < 16; kb2 += 8) {
                        int kq0 = kh * 128 + it * 16 + kb2;
                        uint32_t ahi[4], bw[2];
                        ldsm4(ahi, uA + (rowA_st + kq0) * 4);
                        ldsm2(bw, uW + (rowB0 + kq0) * 4);
                        mma16(acc[0], ahi, bw);
                        ldsm2(bw, uW + (rowB1 + kq0) * 4);
                        mma16(acc[1], ahi, bw);
                        ldsm2(bw, uW + (rowB2 + kq0) * 4);
                        mma16(acc[2], ahi, bw);
                    }
                }
                __syncthreads();
            }

            {
                int rr = wm + (lane >> 2), cc = wn + (lane & 3) * 2;
#pragma unroll
                for (int s = 0; s < 3; s++) {
                    zz[kh * 32 + rr][cc + s * 8]         = acc[s][0];
                    zz[kh * 32 + rr][cc + s * 8 + 1]     = acc[s][1];
                    zz[kh * 32 + rr + 8][cc + s * 8]     = acc[s][2];
                    zz[kh * 32 + rr + 8][cc + s * 8 + 1] = acc[s][3];
                }
            }
            __syncthreads();
            if (stage == 0) {
#pragma unroll
                for (int i = 0; i < 6; i++) {
                    int idx = i * 512 + tid;
                    int bl = idx / 96, c = idx - bl * 96;
                    sz0[bl][c] = zz[bl][c] + zz[32 + bl][c];
                }
                __syncthreads();
            }

#pragma unroll
            for (int p = 0; p < 2; p++) {
                int idx = p * 512 + tid;
                int bl = idx >> 5, hh = idx & 31;
                int b = m0 + bl;
                float zg, zdn, zt;
                if (stage == 0) {
                    zg = sz0[bl][hh]; zdn = sz0[bl][32 + hh]; zt = sz0[bl][64 + hh];
                } else {
                    zg  = sz0[bl][hh]      + zz[bl][hh]      + zz[32 + bl][hh];
                    zdn = sz0[bl][32 + hh] + zz[bl][32 + hh] + zz[32 + bl][32 + hh];
                    zt  = sz0[bl][64 + hh] + zz[bl][64 + hh] + zz[32 + bl][64 + hh];
                }
                float gate = zg + sbase[bl][hh];
                float dyn  = zdn + sbase[bl][32 + hh];
                float tau  = softplusf(zt + sbtau[hh]);
                float hsv  = (stage == 0) ? hreg[p] : (hreg[p] + dd[p]);
                float kd   = (sigmoidf(gate) * tanhf(dyn) - hsv) / (tau + sleak[hh] + 1e-6f);
                float dt   = x_dts[b * TT + t];
                if (stage == 3) {
                    hreg[p] += dt * (rk1[p] + 3.f * rk2[p] + 3.f * rk3[p] + kd) * 0.125f;
                    g_h[b * HH + h0 + hh] = hreg[p];
                    float hi = bfr(hreg[p]);
                    float lo = hreg[p] - hi;
                    float ohi = __shfl_xor_sync(~0u, hi, 1);
                    float olo = __shfl_xor_sync(~0u, lo, 1);
                    if (!(tid & 1)) {
                        g_hHi[b * 256 + ((h0 + hh) >> 1)] = pack_bf2(hi, ohi);
                        g_hLo[b * 256 + ((h0 + hh) >> 1)] = pack_bf2(lo, olo);
                    }
                } else {
                    float dnew;
                    if (stage == 0)      { rk1[p] = kd; dnew = dt * kd * (1.f / 3.f); }
                    else if (stage == 1) { rk2[p] = kd; dnew = dt * (kd - rk1[p] * (1.f / 3.f)); }
                    else                 { rk3[p] = kd; dnew = dt * (rk1[p] - rk2[p] + kd); }
                    dd[p] = dnew;
                    float oth = __shfl_xor_sync(~0u, dnew, 1);
                    if (!(tid & 1)) {
                        uint32_t pk = pack_bf2(dnew, oth);
                        if (stage == 1) g_dB[b * 256 + ((h0 + hh) >> 1)] = pk;
                        else            g_dA[b * 256 + ((h0 + hh) >> 1)] = pk;
                    }
                }
            }
            gbar(gid);
        }
    }

    // ===== final projection =====
    {
        int b = bid * 2 + (tid >> 8);
        int lt = tid & 255;
        if (lt < OO) {
            float acc = b_fc[lt];
#pragma unroll 8
            for (int k = 0; k < HH; k++) acc += g_h[b * HH + k] * W_fc[k * OO + lt];
            out[b * OO + lt] = acc;
        }
    }
}

extern "C" void kernel_launch(void* const* d_in, const int* in_sizes, int n_in,
                              void* d_out, int out_size) {
    const float* x_states = (const float*)d_in[0];
    const float* x_dts    = (const float*)d_in[1];
    const float* Wq = (const float*)d_in[2];  const float* bq = (const float*)d_in[3];
    const float* Wk = (const float*)d_in[4];  const float* bk = (const float*)d_in[5];
    const float* Wv = (const float*)d_in[6];  const float* bv = (const float*)d_in[7];
    const float* W_gd = (const float*)d_in[8]; const float* b_gd = (const float*)d_in[9];
    const float* W_tau = (const float*)d_in[10]; const float* b_tau = (const float*)d_in[11];
    const float* gleak = (const float*)d_in[12]; const float* cm = (const float*)d_in[13];
    const float* W_fc = (const float*)d_in[14]; const float* b_fc = (const float*)d_in[15];
    float* out = (float*)d_out;

    cudaFuncSetAttribute(mega, cudaFuncAttributeMaxDynamicSharedMemorySize, SMEM_BYTES);
    mega<<<NBLK, NTHR, SMEM_BYTES>>>(x_states, x_dts, Wq, bq, Wk, bk, Wv, bv,
                                     W_gd, b_gd, W_tau, b_tau, gleak, cm,
                                     W_fc, b_fc, out);
}

// round 12
// speedup vs baseline: 1.9122x; 1.0685x over previous
#include <cuda_runtime.h>
#include <cuda_bf16.h>
#include <math.h>
#include <stdint.h>

#define BB 256
#define TT 128
#define DD 64
#define HH 512
#define AA 128
#define OO 32
#define NBLK 128
#define NTHR 512

__device__ uint32_t g_Kb[BB * TT * 64];       // K rows packed bf16x2
__device__ float g_V[BB * TT * AA];
__device__ uint32_t g_WBLo[16 * 96 * 256];    // stage lo residual [hg][n][kq]
__device__ uint32_t g_WKVHi[NBLK * 16 * 256]; // per-block KV weight slice
__device__ uint32_t g_WKVLo[NBLK * 16 * 256];
__device__ uint32_t g_WBaseHi[NBLK * 64 * 96]; // per-block base W slice
__device__ uint32_t g_WBaseLo[NBLK * 64 * 96];
__device__ float g_ctx[BB * AA];
__device__ float g_h[BB * HH];
__device__ uint32_t g_hHi[BB * 256];
__device__ uint32_t g_hLo[BB * 256];
__device__ uint32_t g_dA[BB * 256];
__device__ uint32_t g_dB[BB * 256];
__device__ unsigned g_cnt[8 * 32];            // one 128B line per group
__device__ unsigned g_gen[8 * 32];

__device__ __forceinline__ float softplusf(float x) {
    return (x > 20.f) ? x : log1pf(expf(x));
}
__device__ __forceinline__ float sigmoidf(float x) {
    return 1.f / (1.f + expf(-x));
}
__device__ __forceinline__ float bfr(float x) {
    return __bfloat162float(__float2bfloat16(x));
}
__device__ __forceinline__ void mma16(float* d, const uint32_t* a, const uint32_t* b) {
    asm volatile(
        "mma.sync.aligned.m16n8k16.row.col.f32.bf16.bf16.f32 "
        "{%0,%1,%2,%3},{%4,%5,%6,%7},{%8,%9},{%0,%1,%2,%3};"
        : "+f"(d[0]), "+f"(d[1]), "+f"(d[2]), "+f"(d[3])
        : "r"(a[0]), "r"(a[1]), "r"(a[2]), "r"(a[3]), "r"(b[0]), "r"(b[1]));
}
__device__ __forceinline__ uint32_t pack_bf2(float a, float b) {
    __nv_bfloat162 t = __floats2bfloat162_rn(a, b);
    return *(uint32_t*)&t;
}
__device__ __forceinline__ uint32_t s2u(const void* p) {
    return (uint32_t)__cvta_generic_to_shared(p);
}
__device__ __forceinline__ void ldsm4(uint32_t* r, uint32_t a) {
    asm volatile("ldmatrix.sync.aligned.m8n8.x4.shared.b16 {%0,%1,%2,%3}, [%4];"
                 : "=r"(r[0]), "=r"(r[1]), "=r"(r[2]), "=r"(r[3]) : "r"(a));
}
__device__ __forceinline__ void ldsm2(uint32_t* r, uint32_t a) {
    asm volatile("ldmatrix.sync.aligned.m8n8.x2.shared.b16 {%0,%1}, [%2];"
                 : "=r"(r[0]), "=r"(r[1]) : "r"(a));
}

// fence-free acquire/release group barrier (16 blocks), padded counters
__device__ __forceinline__ void gbar(int idx) {
    __syncthreads();
    if (threadIdx.x == 0) {
        unsigned* cntp = &g_cnt[idx * 32];
        unsigned* genp = &g_gen[idx * 32];
        unsigned gen;
        asm volatile("ld.acquire.gpu.global.u32 %0, [%1];" : "=r"(gen) : "l"(genp));
        unsigned old;
        asm volatile("atom.release.gpu.global.add.u32 %0, [%1], %2;"
                     : "=r"(old) : "l"(cntp), "r"(1u));
        if (old == 15u) {
            asm volatile("st.relaxed.gpu.global.u32 [%0], %1;" :: "l"(cntp), "r"(0u));
            asm volatile("st.release.gpu.global.u32 [%0], %1;" :: "l"(genp), "r"(gen + 1u));
        } else {
            unsigned cur = gen;
            while (cur == gen) {
                __nanosleep(32);
                asm volatile("ld.acquire.gpu.global.u32 %0, [%1];" : "=r"(cur) : "l"(genp));
            }
        }
    }
    __syncthreads();
}

#define O_W  0
#define O_A  99840
#define O_AL 133120
#define O_Z  166400
#define O_SB 190976
#define O_SZ 199168
#define SMEM_BYTES 211456

__global__ void __launch_bounds__(NTHR, 1) mega(
    const float* __restrict__ x_states, const float* __restrict__ x_dts,
    const float* __restrict__ Wq, const float* __restrict__ bq,
    const float* __restrict__ Wk, const float* __restrict__ bk,
    const float* __restrict__ Wv, const float* __restrict__ bv,
    const float* __restrict__ W_gd, const float* __restrict__ b_gd,
    const float* __restrict__ W_tau, const float* __restrict__ b_tau,
    const float* __restrict__ gleak, const float* __restrict__ cm,
    const float* __restrict__ W_fc, const float* __restrict__ b_fc,
    float* __restrict__ out)
{
    extern __shared__ char smraw[];
    __shared__ float sleak[32], sbtau[32];
    uint32_t* Ws   = (uint32_t*)(smraw + O_W);
    uint32_t* AsHi = (uint32_t*)(smraw + O_A);
    uint32_t* AsLo = (uint32_t*)(smraw + O_AL);
    float (*zz)[96]    = (float(*)[96])(smraw + O_Z);
    float (*sbase)[64] = (float(*)[64])(smraw + O_SB);
    float (*sz0)[96]   = (float(*)[96])(smraw + O_SZ);
    uint32_t uW  = s2u(smraw + O_W);
    uint32_t uA  = s2u(smraw + O_A);
    uint32_t uAL = s2u(smraw + O_AL);
    uint32_t uZ  = s2u(smraw + O_Z);
    uint32_t uSB = s2u(smraw + O_SB);

    int bid = blockIdx.x, tid = threadIdx.x;
    int lane = tid & 31, wid = tid >> 5;
    int gid = bid >> 4, hg = bid & 15;
    int m0 = gid * 32, h0 = hg * 32;

    // ===== prep =====
    if (tid < 32) {
        sleak[tid] = softplusf(cm[h0 + tid]) + softplusf(gleak[h0 + tid]);
        sbtau[tid] = b_tau[h0 + tid];
    }
    for (int idx = tid; idx < 96 * 256; idx += NTHR) {
        int n = idx >> 8, kq = idx & 255, k0 = kq * 2;
        float w0, w1;
        if (n < 32)      { w0 = W_gd[(64 + k0) * 1024 + h0 + n];       w1 = W_gd[(65 + k0) * 1024 + h0 + n]; }
        else if (n < 64) { w0 = W_gd[(64 + k0) * 1024 + 512 + h0 + n - 32]; w1 = W_gd[(65 + k0) * 1024 + 512 + h0 + n - 32]; }
        else             { w0 = W_tau[k0 * 512 + h0 + n - 64];         w1 = W_tau[(k0 + 1) * 512 + h0 + n - 64]; }
        float a = bfr(w0), b = bfr(w1);
        Ws[n * 260 + kq] = pack_bf2(a, b);
        g_WBLo[(hg * 96 + n) * 256 + kq] = pack_bf2(w0 - a, w1 - b);
    }
    for (int idx = tid; idx < 16 * 256; idx += NTHR) {
        int n = idx >> 8, kq = idx & 255, k0 = kq * 2;
        int nn = hg * 16 + n, ncol = nn & 127;
        const float* W = (nn < 128) ? Wk : Wv;
        float w0 = W[k0 * 128 + ncol], w1 = W[(k0 + 1) * 128 + ncol];
        float a = bfr(w0), b = bfr(w1);
        g_WKVHi[(bid * 16 + n) * 256 + kq] = pack_bf2(a, b);
        g_WKVLo[(bid * 16 + n) * 256 + kq] = pack_bf2(w0 - a, w1 - b);
    }
    for (int idx = tid; idx < 64 * 96; idx += NTHR) {
        int n = idx / 96, kq = idx - n * 96, k0 = kq * 2;
        int row0 = (k0 < 64) ? k0 : (k0 + 512);
        int col = (n < 32) ? (h0 + n) : (512 + h0 + n - 32);
        float w0 = W_gd[row0 * 1024 + col], w1 = W_gd[(row0 + 1) * 1024 + col];
        float a = bfr(w0), b = bfr(w1);
        g_WBaseHi[(bid * 64 + n) * 96 + kq] = pack_bf2(a, b);
        g_WBaseLo[(bid * 64 + n) * 96 + kq] = pack_bf2(w0 - a, w1 - b);
    }
    for (int idx = tid; idx < 32 * HH; idx += NTHR) g_h[m0 * HH + idx] = 0.f;
    {
        int mzr = tid >> 4, czc = tid & 15;
        g_hHi[(m0 + mzr) * 256 + hg * 16 + czc] = 0;
        g_hLo[(m0 + mzr) * 256 + hg * 16 + czc] = 0;
    }
    gbar(gid);

    float hreg[2] = {0.f, 0.f}, rk1[2], rk2[2], rk3[2], dd[2];
    int kh = wid >> 3, wl = wid & 7;
    int wm = (wl >> 2) * 16, wn = (wl & 3) * 24;
    int qa = lane & 3;
    int aSel = (lane >> 4) << 2;
    int bSel = ((lane >> 3) & 1) << 2;
    int rowA_st = (wm + (lane & 15)) * 260 + aSel;
    int rowB0 = (wn + 0 * 8 + (lane & 7)) * 260 + bSel;
    int rowB1 = (wn + 1 * 8 + (lane & 7)) * 260 + bSel;
    int rowB2 = (wn + 2 * 8 + (lane & 7)) * 260 + bSel;
    long loN0 = (long)(hg * 96 + wn + 0 * 8 + (lane >> 2)) * 256 + qa;
    long loN1 = (long)(hg * 96 + wn + 1 * 8 + (lane >> 2)) * 256 + qa;
    long loN2 = (long)(hg * 96 + wn + 2 * 8 + (lane >> 2)) * 256 + qa;
    int wkn = wid & 1, wkm = (wid >> 1) & 1, wks = wid >> 2;
    int rowA_kv = (wkm * 16 + (lane & 15)) * 260 + aSel;
    int rowB_kv = (wkn * 8 + (lane & 7)) * 260 + bSel;
    int wbk = wid >> 2, wbm = (wid >> 1) & 1, wbn = wid & 1;
    int rowA_bs = (wbm * 16 + (lane & 15)) * 260 + aSel;

    for (int t = 0; t < TT; t++) {
        // ---- KV (tensorized): row t-1 ----
        if (t > 0) {
#pragma unroll
            for (int i = 0; i < 4; i++) {
                int u4 = i * 512 + tid;
                int m = u4 >> 6, q4 = u4 & 63;
                *(uint4*)&AsHi[m * 260 + q4 * 4] = ((const uint4*)&g_hHi[(m0 + m) * 256])[q4];
                *(uint4*)&AsLo[m * 260 + q4 * 4] = ((const uint4*)&g_hLo[(m0 + m) * 256])[q4];
            }
            uint32_t* Bh = (uint32_t*)(smraw + O_Z);
            uint32_t* Bl = (uint32_t*)(smraw + O_SB);
#pragma unroll
            for (int i = 0; i < 2; i++) {
                int u4 = i * 512 + tid;
                int n = u4 >> 6, q4 = u4 & 63;
                *(uint4*)&Bh[n * 260 + q4 * 4] = ((const uint4*)&g_WKVHi[(bid * 16 + n) * 256])[q4];
                *(uint4*)&Bl[n * 260 + q4 * 4] = ((const uint4*)&g_WKVLo[(bid * 16 + n) * 256])[q4];
            }
            __syncthreads();
            float acc[4] = {0.f, 0.f, 0.f, 0.f};
#pragma unroll
            for (int it = 0; it < 8; it++) {
                int kq0 = wks * 64 + it * 8;
                uint32_t ahi[4], alo[4], bhi[2], blo[2];
                ldsm4(ahi, uA  + (rowA_kv + kq0) * 4);
                ldsm4(alo, uAL + (rowA_kv + kq0) * 4);
                ldsm2(bhi, uZ  + (rowB_kv + kq0) * 4);
                ldsm2(blo, uSB + (rowB_kv + kq0) * 4);
                mma16(acc, ahi, bhi);
                mma16(acc, alo, bhi);
                mma16(acc, ahi, blo);
            }
            __syncthreads();
            float* pkv = (float*)(smraw + O_AL);
            {
                int ml = wkm * 16 + (lane >> 2), nl = wkn * 8 + (lane & 3) * 2;
                int off = wks * 512 + ml * 16 + nl;
                pkv[off] = acc[0]; pkv[off + 1] = acc[1];
                pkv[off + 128] = acc[2]; pkv[off + 129] = acc[3];
            }
            __syncthreads();
            {
                int m = tid >> 4, n = tid & 15;
                float s = pkv[m * 16 + n] + pkv[512 + m * 16 + n] +
                          pkv[1024 + m * 16 + n] + pkv[1536 + m * 16 + n];
                if (hg < 8) {
                    int ncol = hg * 16 + n;
                    s += bk[ncol];
                    float os = __shfl_xor_sync(~0u, s, 1);
                    if (!(tid & 1))
                        g_Kb[((m0 + m) * TT + (t - 1)) * 64 + (ncol >> 1)] = pack_bf2(s, os);
                } else {
                    int ncol = (hg - 8) * 16 + n;
                    s += bv[ncol];
                    g_V[((m0 + m) * TT + (t - 1)) * AA + ncol] = s;
                }
            }
            gbar(gid);
        }

        // ---- ATTN ----
        {
            float* aq   = (float*)(smraw + O_A);
            float* asc  = aq + 256;
            float* actx = asc + 256;
            float* axs  = actx + 512;
            float* ared = axs + 128;
            int hB = tid >> 8, lt = tid & 255;
            int b = bid * 2 + hB;
            if (t == 0) {
                if (lt < 128) g_ctx[b * AA + lt] = 0.f;
            } else {
                if (lt < DD) axs[hB * 64 + lt] = x_states[(b * TT + t) * DD + lt];
                __syncthreads();
                if (lt < 128) {
                    float qv = bq[lt];
#pragma unroll 16
                    for (int d = 0; d < DD; d++) qv += axs[hB * 64 + d] * Wq[d * AA + lt];
                    aq[hB * 128 + lt] = qv;
                }
                __syncthreads();
                float s = -1e30f;
                if (lt < t) {
                    const uint4* Kp = (const uint4*)&g_Kb[(b * TT + lt) * 64];
                    const float* qh = &aq[hB * 128];
                    float dot = 0.f;
#pragma unroll
                    for (int i = 0; i < 16; i++) {
                        uint4 kv = Kp[i];
                        float2 f;
                        f = __bfloat1622float2(*(__nv_bfloat162*)&kv.x);
                        dot += f.x * qh[i * 8 + 0] + f.y * qh[i * 8 + 1];
                        f = __bfloat1622float2(*(__nv_bfloat162*)&kv.y);
                        dot += f.x * qh[i * 8 + 2] + f.y * qh[i * 8 + 3];
                        f = __bfloat1622float2(*(__nv_bfloat162*)&kv.z);
                        dot += f.x * qh[i * 8 + 4] + f.y * qh[i * 8 + 5];
                        f = __bfloat1622float2(*(__nv_bfloat162*)&kv.w);
                        dot += f.x * qh[i * 8 + 6] + f.y * qh[i * 8 + 7];
                    }
                    s = dot * (1.f / 11.313708498984761f);
                }
                float m = s;
#pragma unroll
                for (int o = 16; o > 0; o >>= 1) m = fmaxf(m, __shfl_xor_sync(~0u, m, o));
                if (lane == 0) ared[hB * 8 + (wid & 7)] = m;
                __syncthreads();
                m = ared[hB * 8];
#pragma unroll
                for (int i = 1; i < 8; i++) m = fmaxf(m, ared[hB * 8 + i]);
                float e = (lt < t) ? expf(s - m) : 0.f;
                float su = e;
#pragma unroll
                for (int o = 16; o > 0; o >>= 1) su += __shfl_xor_sync(~0u, su, o);
                __syncthreads();
                if (lane == 0) ared[hB * 8 + (wid & 7)] = su;
                __syncthreads();
                su = 0.f;
#pragma unroll
                for (int i = 0; i < 8; i++) su += ared[hB * 8 + i];
                if (lt < 128) asc[hB * 128 + lt] = (lt < t) ? (e / su) : 0.f;
                __syncthreads();
                {
                    int a = lt & 127, th = lt >> 7;
                    int tlim = (t + 7) & ~7;
                    float c = 0.f;
#pragma unroll 8
                    for (int sx = th; sx < tlim; sx += 2)
                        c += asc[hB * 128 + sx] * g_V[(b * TT + sx) * AA + a];
                    actx[(hB * 2 + th) * 128 + a] = c;
                }
                __syncthreads();
                if (lt < 128)
                    g_ctx[b * AA + lt] = actx[hB * 256 + lt] + actx[hB * 256 + 128 + lt];
            }
            gbar(gid);
        }

        // ---- 4 RK stages ----
        for (int stage = 0; stage < 4; stage++) {
            float acc[3][4];
#pragma unroll
            for (int s = 0; s < 3; s++)
#pragma unroll
                for (int i = 0; i < 4; i++) acc[s][i] = 0.f;

            if (stage == 0) {
#pragma unroll
                for (int i = 0; i < 6; i++) {
                    int idx = i * 512 + tid;
                    int m = idx / 96, kq = idx - m * 96;
                    int k0 = kq * 2;
                    float a0, a1;
                    if (kq < 32) {
                        const float* xr = &x_states[((m0 + m) * TT + t) * DD];
                        a0 = xr[k0]; a1 = xr[k0 + 1];
                    } else {
                        const float* cr = &g_ctx[(m0 + m) * AA];
                        a0 = cr[k0 - 64]; a1 = cr[k0 - 63];
                    }
                    float h0v = bfr(a0), h1v = bfr(a1);
                    AsHi[m * 260 + kq] = pack_bf2(h0v, h1v);
                    AsLo[m * 260 + kq] = pack_bf2(a0 - h0v, a1 - h1v);
                }
                __syncthreads();
                {
                    float accb[4][4];
#pragma unroll
                    for (int s = 0; s < 4; s++)
#pragma unroll
                        for (int i = 0; i < 4; i++) accb[s][i] = 0.f;
#pragma unroll
                    for (int ks = 0; ks < 3; ks++) {
                        int kq0 = wbk * 24 + ks * 8;
                        uint32_t ahi[4], alo[4];
                        ldsm4(ahi, uA  + (rowA_bs + kq0) * 4);
                        ldsm4(alo, uAL + (rowA_bs + kq0) * 4);
#pragma unroll
                        for (int s = 0; s < 4; s++) {
                            int nrow = wbn * 32 + s * 8 + (lane >> 2);
                            long bix = (long)(bid * 64 + nrow) * 96 + kq0 + qa;
                            uint32_t bhi[2], blo[2];
                            bhi[0] = g_WBaseHi[bix]; bhi[1] = g_WBaseHi[bix + 4];
                            blo[0] = g_WBaseLo[bix]; blo[1] = g_WBaseLo[bix + 4];
                            mma16(accb[s], ahi, bhi);
                            mma16(accb[s], alo, bhi);
                            mma16(accb[s], ahi, blo);
                        }
                    }
                    __syncthreads();
                    float* pb = (float*)(smraw + O_AL);
#pragma unroll
                    for (int s = 0; s < 4; s++) {
                        int off = wbk * 2048 + (wbm * 16 + (lane >> 2)) * 64 +
                                  wbn * 32 + s * 8 + (lane & 3) * 2;
                        pb[off] = accb[s][0]; pb[off + 1] = accb[s][1];
                        pb[off + 512] = accb[s][2]; pb[off + 513] = accb[s][3];
                    }
                    __syncthreads();
#pragma unroll
                    for (int i = 0; i < 4; i++) {
                        int idx = i * 512 + tid;
                        int m = idx >> 6, n = idx & 63;
                        int col = (n < 32) ? (h0 + n) : (512 + h0 + n - 32);
                        sbase[m][n] = pb[m * 64 + n] + pb[2048 + m * 64 + n] +
                                      pb[4096 + m * 64 + n] + pb[6144 + m * 64 + n] +
                                      b_gd[col];
                    }
                }
                __syncthreads();
#pragma unroll
                for (int i = 0; i < 4; i++) {
                    int u4 = i * 512 + tid;
                    int m = u4 >> 6, q4 = u4 & 63;
                    *(uint4*)&AsHi[m * 260 + q4 * 4] = ((const uint4*)&g_hHi[(m0 + m) * 256])[q4];
                    *(uint4*)&AsLo[m * 260 + q4 * 4] = ((const uint4*)&g_hLo[(m0 + m) * 256])[q4];
                }
                __syncthreads();
#pragma unroll
                for (int it = 0; it < 8; it++) {
#pragma unroll
                    for (int kb2 = 0; kb2 < 16; kb2 += 8) {
                        int kq0 = kh * 128 + it * 16 + kb2;
                        uint32_t ahi[4], alo[4], bw[2], bl[2];
                        ldsm4(ahi, uA  + (rowA_st + kq0) * 4);
                        ldsm4(alo, uAL + (rowA_st + kq0) * 4);
                        ldsm2(bw, uW + (rowB0 + kq0) * 4);
                        bl[0] = g_WBLo[loN0 + kq0]; bl[1] = g_WBLo[loN0 + kq0 + 4];
                        mma16(acc[0], ahi, bw); mma16(acc[0], alo, bw); mma16(acc[0], ahi, bl);
                        ldsm2(bw, uW + (rowB1 + kq0) * 4);
                        bl[0] = g_WBLo[loN1 + kq0]; bl[1] = g_WBLo[loN1 + kq0 + 4];
                        mma16(acc[1], ahi, bw); mma16(acc[1], alo, bw); mma16(acc[1], ahi, bl);
                        ldsm2(bw, uW + (rowB2 + kq0) * 4);
                        bl[0] = g_WBLo[loN2 + kq0]; bl[1] = g_WBLo[loN2 + kq0 + 4];
                        mma16(acc[2], ahi, bw); mma16(acc[2], alo, bw); mma16(acc[2], ahi, bl);
                    }
                }
                __syncthreads();
            } else {
                const uint32_t* Dg = (stage == 2) ? g_dB : g_dA;
#pragma unroll
                for (int i = 0; i < 4; i++) {
                    int idx = i * 512 + tid;
                    int m = idx >> 6, q4 = idx & 63;
                    *(uint4*)&AsHi[m * 260 + q4 * 4] = ((const uint4*)&Dg[(m0 + m) * 256])[q4];
                }
                __syncthreads();
#pragma unroll
                for (int it = 0; it < 8; it++) {
#pragma unroll
                    for (int kb2 = 0; kb2 < 16; kb2 += 8) {
                        int kq0 = kh * 128 + it * 16 + kb2;
                        uint32_t ahi[4], bw[2];
                        ldsm4(ahi, uA + (rowA_st + kq0) * 4);
                        ldsm2(bw, uW + (rowB0 + kq0) * 4);
                        mma16(acc[0], ahi, bw);
                        ldsm2(bw, uW + (rowB1 + kq0) * 4);
                        mma16(acc[1], ahi, bw);
                        ldsm2(bw, uW + (rowB2 + kq0) * 4);
                        mma16(acc[2], ahi, bw);
                    }
                }
                __syncthreads();
            }

            {
                int rr = wm + (lane >> 2), cc = wn + (lane & 3) * 2;
#pragma unroll
                for (int s = 0; s < 3; s++) {
                    zz[kh * 32 + rr][cc + s * 8]         = acc[s][0];
                    zz[kh * 32 + rr][cc + s * 8 + 1]     = acc[s][1];
                    zz[kh * 32 + rr + 8][cc + s * 8]     = acc[s][2];
                    zz[kh * 32 + rr + 8][cc + s * 8 + 1] = acc[s][3];
                }
            }
            __syncthreads();
            if (stage == 0) {
#pragma unroll
                for (int i = 0; i < 6; i++) {
                    int idx = i * 512 + tid;
                    int bl = idx / 96, c = idx - bl * 96;
                    sz0[bl][c] = zz[bl][c] + zz[32 + bl][c];
                }
                __syncthreads();
            }

#pragma unroll
            for (int p = 0; p < 2; p++) {
                int idx = p * 512 + tid;
                int bl = idx >> 5, hh = idx & 31;
                int b = m0 + bl;
                float zg, zdn, zt;
                if (stage == 0) {
                    zg = sz0[bl][hh]; zdn = sz0[bl][32 + hh]; zt = sz0[bl][64 + hh];
                } else {
                    zg  = sz0[bl][hh]      + zz[bl][hh]      + zz[32 + bl][hh];
                    zdn = sz0[bl][32 + hh] + zz[bl][32 + hh] + zz[32 + bl][32 + hh];
                    zt  = sz0[bl][64 + hh] + zz[bl][64 + hh] + zz[32 + bl][64 + hh];
                }
                float gate = zg + sbase[bl][hh];
                float dyn  = zdn + sbase[bl][32 + hh];
                float tau  = softplusf(zt + sbtau[hh]);
                float hsv  = (stage == 0) ? hreg[p] : (hreg[p] + dd[p]);
                float kd   = (sigmoidf(gate) * tanhf(dyn) - hsv) / (tau + sleak[hh] + 1e-6f);
                float dt   = x_dts[b * TT + t];
                if (stage == 3) {
                    hreg[p] += dt * (rk1[p] + 3.f * rk2[p] + 3.f * rk3[p] + kd) * 0.125f;
                    g_h[b * HH + h0 + hh] = hreg[p];
                    float hi = bfr(hreg[p]);
                    float lo = hreg[p] - hi;
                    float ohi = __shfl_xor_sync(~0u, hi, 1);
                    float olo = __shfl_xor_sync(~0u, lo, 1);
                    if (!(tid & 1)) {
                        g_hHi[b * 256 + ((h0 + hh) >> 1)] = pack_bf2(hi, ohi);
                        g_hLo[b * 256 + ((h0 + hh) >> 1)] = pack_bf2(lo, olo);
                    }
                } else {
                    float dnew;
                    if (stage == 0)      { rk1[p] = kd; dnew = dt * kd * (1.f / 3.f); }
                    else if (stage == 1) { rk2[p] = kd; dnew = dt * (kd - rk1[p] * (1.f / 3.f)); }
                    else                 { rk3[p] = kd; dnew = dt * (rk1[p] - rk2[p] + kd); }
                    dd[p] = dnew;
                    float oth = __shfl_xor_sync(~0u, dnew, 1);
                    if (!(tid & 1)) {
                        uint32_t pk = pack_bf2(dnew, oth);
                        if (stage == 1) g_dB[b * 256 + ((h0 + hh) >> 1)] = pk;
                        else            g_dA[b * 256 + ((h0 + hh) >> 1)] = pk;
                    }
                }
            }
            gbar(gid);
        }
    }

    // ===== final projection =====
    {
        int b = bid * 2 + (tid >> 8);
        int lt = tid & 255;
        if (lt < OO) {
            float acc = b_fc[lt];
#pragma unroll 8
            for (int k = 0; k < HH; k++) acc += g_h[b * HH + k] * W_fc[k * OO + lt];
            out[b * OO + lt] = acc;
        }
    }
}

extern "C" void kernel_launch(void* const* d_in, const int* in_sizes, int n_in,
                              void* d_out, int out_size) {
    const float* x_states = (const float*)d_in[0];
    const float* x_dts    = (const float*)d_in[1];
    const float* Wq = (const float*)d_in[2];  const float* bq = (const float*)d_in[3];
    const float* Wk = (const float*)d_in[4];  const float* bk = (const float*)d_in[5];
    const float* Wv = (const float*)d_in[6];  const float* bv = (const float*)d_in[7];
    const float* W_gd = (const float*)d_in[8]; const float* b_gd = (const float*)d_in[9];
    const float* W_tau = (const float*)d_in[10]; const float* b_tau = (const float*)d_in[11];
    const float* gleak = (const float*)d_in[12]; const float* cm = (const float*)d_in[13];
    const float* W_fc = (const float*)d_in[14]; const float* b_fc = (const float*)d_in[15];
    float* out = (float*)d_out;

    cudaFuncSetAttribute(mega, cudaFuncAttributeMaxDynamicSharedMemorySize, SMEM_BYTES);
    mega<<<NBLK, NTHR, SMEM_BYTES>>>(x_states, x_dts, Wq, bq, Wk, bk, Wv, bv,
                                     W_gd, b_gd, W_tau, b_tau, gleak, cm,
                                     W_fc, b_fc, out);
}

// round 13
// speedup vs baseline: 1.9173x; 1.0026x over previous
#include <cuda_runtime.h>
#include <cuda_bf16.h>
#include <math.h>
#include <stdint.h>

#define BB 256
#define TT 128
#define DD 64
#define HH 512
#define AA 128
#define OO 32
#define NBLK 128
#define NTHR 512

__device__ uint32_t g_KbT[BB * 64 * TT];      // K transposed: [(b*64+j)*128 + t], bf16x2 over a
__device__ float g_V[BB * TT * AA];
__device__ uint32_t g_WBLo[16 * 96 * 256];    // stage lo residual [hg][n][kq]
__device__ uint32_t g_WKVHi[NBLK * 16 * 256];
__device__ uint32_t g_WKVLo[NBLK * 16 * 256];
__device__ uint32_t g_WBaseHi[NBLK * 64 * 96];
__device__ uint32_t g_WBaseLo[NBLK * 64 * 96];
__device__ float g_ctx[BB * AA];
__device__ float g_h[BB * HH];
__device__ uint32_t g_hHi[BB * 256];
__device__ uint32_t g_hLo[BB * 256];
__device__ uint32_t g_dA[BB * 256];
__device__ uint32_t g_dB[BB * 256];
__device__ unsigned g_cnt[8 * 32];
__device__ unsigned g_gen[8 * 32];

__device__ __forceinline__ float softplusf(float x) {
    return (x > 20.f) ? x : log1pf(expf(x));
}
__device__ __forceinline__ float sigmoidf(float x) {
    return 1.f / (1.f + expf(-x));
}
__device__ __forceinline__ float bfr(float x) {
    return __bfloat162float(__float2bfloat16(x));
}
__device__ __forceinline__ void mma16(float* d, const uint32_t* a, const uint32_t* b) {
    asm volatile(
        "mma.sync.aligned.m16n8k16.row.col.f32.bf16.bf16.f32 "
        "{%0,%1,%2,%3},{%4,%5,%6,%7},{%8,%9},{%0,%1,%2,%3};"
        : "+f"(d[0]), "+f"(d[1]), "+f"(d[2]), "+f"(d[3])
        : "r"(a[0]), "r"(a[1]), "r"(a[2]), "r"(a[3]), "r"(b[0]), "r"(b[1]));
}
__device__ __forceinline__ uint32_t pack_bf2(float a, float b) {
    __nv_bfloat162 t = __floats2bfloat162_rn(a, b);
    return *(uint32_t*)&t;
}
__device__ __forceinline__ uint32_t s2u(const void* p) {
    return (uint32_t)__cvta_generic_to_shared(p);
}
__device__ __forceinline__ void ldsm4(uint32_t* r, uint32_t a) {
    asm volatile("ldmatrix.sync.aligned.m8n8.x4.shared.b16 {%0,%1,%2,%3}, [%4];"
                 : "=r"(r[0]), "=r"(r[1]), "=r"(r[2]), "=r"(r[3]) : "r"(a));
}
__device__ __forceinline__ void ldsm2(uint32_t* r, uint32_t a) {
    asm volatile("ldmatrix.sync.aligned.m8n8.x2.shared.b16 {%0,%1}, [%2];"
                 : "=r"(r[0]), "=r"(r[1]) : "r"(a));
}

__device__ __forceinline__ void gbar(int idx) {
    __syncthreads();
    if (threadIdx.x == 0) {
        unsigned* cntp = &g_cnt[idx * 32];
        unsigned* genp = &g_gen[idx * 32];
        unsigned gen;
        asm volatile("ld.acquire.gpu.global.u32 %0, [%1];" : "=r"(gen) : "l"(genp));
        unsigned old;
        asm volatile("atom.release.gpu.global.add.u32 %0, [%1], %2;"
                     : "=r"(old) : "l"(cntp), "r"(1u));
        if (old == 15u) {
            asm volatile("st.relaxed.gpu.global.u32 [%0], %1;" :: "l"(cntp), "r"(0u));
            asm volatile("st.release.gpu.global.u32 [%0], %1;" :: "l"(genp), "r"(gen + 1u));
        } else {
            unsigned cur = gen;
            while (cur == gen) {
                __nanosleep(32);
                asm volatile("ld.acquire.gpu.global.u32 %0, [%1];" : "=r"(cur) : "l"(genp));
            }
        }
    }
    __syncthreads();
}

#define O_W  0
#define O_A  99840
#define O_AL 133120
#define O_Z  166400
#define O_SB 190976
#define O_SZ 199168
#define O_PB 211456          // base A lo (stride-100), 12800 B
#define SMEM_BYTES 224256

__global__ void __launch_bounds__(NTHR, 1) mega(
    const float* __restrict__ x_states, const float* __restrict__ x_dts,
    const float* __restrict__ Wq, const float* __restrict__ bq,
    const float* __restrict__ Wk, const float* __restrict__ bk,
    const float* __restrict__ Wv, const float* __restrict__ bv,
    const float* __restrict__ W_gd, const float* __restrict__ b_gd,
    const float* __restrict__ W_tau, const float* __restrict__ b_tau,
    const float* __restrict__ gleak, const float* __restrict__ cm,
    const float* __restrict__ W_fc, const float* __restrict__ b_fc,
    float* __restrict__ out)
{
    extern __shared__ char smraw[];
    __shared__ float sleak[32], sbtau[32];
    uint32_t* Ws   = (uint32_t*)(smraw + O_W);
    uint32_t* AsHi = (uint32_t*)(smraw + O_A);
    uint32_t* AsLo = (uint32_t*)(smraw + O_AL);
    float (*zz)[96]    = (float(*)[96])(smraw + O_Z);
    float (*sbase)[64] = (float(*)[64])(smraw + O_SB);
    float (*sz0)[96]   = (float(*)[96])(smraw + O_SZ);
    uint32_t uW  = s2u(smraw + O_W);
    uint32_t uA  = s2u(smraw + O_A);
    uint32_t uAL = s2u(smraw + O_AL);
    uint32_t uZ  = s2u(smraw + O_Z);
    uint32_t uSB = s2u(smraw + O_SB);
    uint32_t uPB = s2u(smraw + O_PB);

    int bid = blockIdx.x, tid = threadIdx.x;
    int lane = tid & 31, wid = tid >> 5;
    int gid = bid >> 4, hg = bid & 15;
    int m0 = gid * 32, h0 = hg * 32;

    // ===== prep =====
    if (tid < 32) {
        sleak[tid] = softplusf(cm[h0 + tid]) + softplusf(gleak[h0 + tid]);
        sbtau[tid] = b_tau[h0 + tid];
    }
    for (int idx = tid; idx < 96 * 256; idx += NTHR) {
        int n = idx >> 8, kq = idx & 255, k0 = kq * 2;
        float w0, w1;
        if (n < 32)      { w0 = W_gd[(64 + k0) * 1024 + h0 + n];       w1 = W_gd[(65 + k0) * 1024 + h0 + n]; }
        else if (n < 64) { w0 = W_gd[(64 + k0) * 1024 + 512 + h0 + n - 32]; w1 = W_gd[(65 + k0) * 1024 + 512 + h0 + n - 32]; }
        else             { w0 = W_tau[k0 * 512 + h0 + n - 64];         w1 = W_tau[(k0 + 1) * 512 + h0 + n - 64]; }
        float a = bfr(w0), b = bfr(w1);
        Ws[n * 260 + kq] = pack_bf2(a, b);
        g_WBLo[(hg * 96 + n) * 256 + kq] = pack_bf2(w0 - a, w1 - b);
    }
    for (int idx = tid; idx < 16 * 256; idx += NTHR) {
        int n = idx >> 8, kq = idx & 255, k0 = kq * 2;
        int nn = hg * 16 + n, ncol = nn & 127;
        const float* W = (nn < 128) ? Wk : Wv;
        float w0 = W[k0 * 128 + ncol], w1 = W[(k0 + 1) * 128 + ncol];
        float a = bfr(w0), b = bfr(w1);
        g_WKVHi[(bid * 16 + n) * 256 + kq] = pack_bf2(a, b);
        g_WKVLo[(bid * 16 + n) * 256 + kq] = pack_bf2(w0 - a, w1 - b);
    }
    for (int idx = tid; idx < 64 * 96; idx += NTHR) {
        int n = idx / 96, kq = idx - n * 96, k0 = kq * 2;
        int row0 = (k0 < 64) ? k0 : (k0 + 512);
        int col = (n < 32) ? (h0 + n) : (512 + h0 + n - 32);
        float w0 = W_gd[row0 * 1024 + col], w1 = W_gd[(row0 + 1) * 1024 + col];
        float a = bfr(w0), b = bfr(w1);
        g_WBaseHi[(bid * 64 + n) * 96 + kq] = pack_bf2(a, b);
        g_WBaseLo[(bid * 64 + n) * 96 + kq] = pack_bf2(w0 - a, w1 - b);
    }
    for (int idx = tid; idx < 32 * HH; idx += NTHR) g_h[m0 * HH + idx] = 0.f;
    {
        int mzr = tid >> 4, czc = tid & 15;
        g_hHi[(m0 + mzr) * 256 + hg * 16 + czc] = 0;
        g_hLo[(m0 + mzr) * 256 + hg * 16 + czc] = 0;
    }
    gbar(gid);

    float hreg[2] = {0.f, 0.f}, rk1[2], rk2[2], rk3[2], dd[2];
    int kh = wid >> 3, wl = wid & 7;
    int wm = (wl >> 2) * 16, wn = (wl & 3) * 24;
    int qa = lane & 3;
    int aSel = (lane >> 4) << 2;
    int bSel = ((lane >> 3) & 1) << 2;
    int rowA_st = (wm + (lane & 15)) * 260 + aSel;
    int rowB0 = (wn + 0 * 8 + (lane & 7)) * 260 + bSel;
    int rowB1 = (wn + 1 * 8 + (lane & 7)) * 260 + bSel;
    int rowB2 = (wn + 2 * 8 + (lane & 7)) * 260 + bSel;
    long loN0 = (long)(hg * 96 + wn + 0 * 8 + (lane >> 2)) * 256 + qa;
    long loN1 = (long)(hg * 96 + wn + 1 * 8 + (lane >> 2)) * 256 + qa;
    long loN2 = (long)(hg * 96 + wn + 2 * 8 + (lane >> 2)) * 256 + qa;
    int wkn = wid & 1, wkm = (wid >> 1) & 1, wks = wid >> 2;
    int rowA_kv = (wkm * 16 + (lane & 15)) * 260 + aSel;
    int rowB_kv = (wkn * 8 + (lane & 7)) * 260 + bSel;
    // base warp mapping: 2k x 2m x 4n, warp tile 16m x 16n x 96elem-k
    int wbk2 = wid >> 3, wbm2 = (wid >> 2) & 1, wbn2 = wid & 3;
    int rowA_bs = (wbm2 * 16 + (lane & 15)) * 100 + aSel;

    for (int t = 0; t < TT; t++) {
        // ---- KV (tensorized): row t-1; A(h) staged into AsHi/AsLo, PRESERVED to stage0 ----
        if (t > 0) {
#pragma unroll
            for (int i = 0; i < 4; i++) {
                int u4 = i * 512 + tid;
                int m = u4 >> 6, q4 = u4 & 63;
                *(uint4*)&AsHi[m * 260 + q4 * 4] = ((const uint4*)&g_hHi[(m0 + m) * 256])[q4];
                *(uint4*)&AsLo[m * 260 + q4 * 4] = ((const uint4*)&g_hLo[(m0 + m) * 256])[q4];
            }
            uint32_t* Bh = (uint32_t*)(smraw + O_Z);
            uint32_t* Bl = (uint32_t*)(smraw + O_SB);
#pragma unroll
            for (int i = 0; i < 2; i++) {
                int u4 = i * 512 + tid;
                int n = u4 >> 6, q4 = u4 & 63;
                *(uint4*)&Bh[n * 260 + q4 * 4] = ((const uint4*)&g_WKVHi[(bid * 16 + n) * 256])[q4];
                *(uint4*)&Bl[n * 260 + q4 * 4] = ((const uint4*)&g_WKVLo[(bid * 16 + n) * 256])[q4];
            }
            __syncthreads();
            float acc[4] = {0.f, 0.f, 0.f, 0.f};
#pragma unroll
            for (int it = 0; it < 8; it++) {
                int kq0 = wks * 64 + it * 8;
                uint32_t ahi[4], alo[4], bhi[2], blo[2];
                ldsm4(ahi, uA  + (rowA_kv + kq0) * 4);
                ldsm4(alo, uAL + (rowA_kv + kq0) * 4);
                ldsm2(bhi, uZ  + (rowB_kv + kq0) * 4);
                ldsm2(blo, uSB + (rowB_kv + kq0) * 4);
                mma16(acc, ahi, bhi);
                mma16(acc, alo, bhi);
                mma16(acc, ahi, blo);
            }
            __syncthreads();
            float* pkv = (float*)(smraw + O_SZ);   // moved off AsLo
            {
                int ml = wkm * 16 + (lane >> 2), nl = wkn * 8 + (lane & 3) * 2;
                int off = wks * 512 + ml * 16 + nl;
                pkv[off] = acc[0]; pkv[off + 1] = acc[1];
                pkv[off + 128] = acc[2]; pkv[off + 129] = acc[3];
            }
            __syncthreads();
            {
                int m = tid >> 4, n = tid & 15;
                float s = pkv[m * 16 + n] + pkv[512 + m * 16 + n] +
                          pkv[1024 + m * 16 + n] + pkv[1536 + m * 16 + n];
                if (hg < 8) {
                    int ncol = hg * 16 + n;
                    s += bk[ncol];
                    float os = __shfl_xor_sync(~0u, s, 1);
                    if (!(tid & 1))
                        g_KbT[((m0 + m) * 64 + (ncol >> 1)) * TT + (t - 1)] = pack_bf2(s, os);
                } else {
                    int ncol = (hg - 8) * 16 + n;
                    s += bv[ncol];
                    g_V[((m0 + m) * TT + (t - 1)) * AA + ncol] = s;
                }
            }
            gbar(gid);
        }

        // ---- ATTN: scratch in O_SZ region (keeps AsHi/AsLo intact) ----
        {
            float* aq   = (float*)(smraw + O_SZ);
            float* asc  = aq + 256;
            float* actx = asc + 256;
            float* axs  = actx + 512;
            float* ared = axs + 128;
            int hB = tid >> 8, lt = tid & 255;
            int b = bid * 2 + hB;
            if (t == 0) {
                if (lt < 128) g_ctx[b * AA + lt] = 0.f;
            } else {
                if (lt < DD) axs[hB * 64 + lt] = x_states[(b * TT + t) * DD + lt];
                __syncthreads();
                if (lt < 128) {
                    float qv = bq[lt];
#pragma unroll 16
                    for (int d = 0; d < DD; d++) qv += axs[hB * 64 + d] * Wq[d * AA + lt];
                    aq[hB * 128 + lt] = qv;
                }
                __syncthreads();
                float s = -1e30f;
                if (lt < t) {
                    const uint32_t* Kp = &g_KbT[b * 64 * TT + lt];
                    const float* qh = &aq[hB * 128];
                    float dot = 0.f;
#pragma unroll 8
                    for (int j = 0; j < 64; j++) {
                        uint32_t kv = Kp[j * TT];
                        float2 f = __bfloat1622float2(*(__nv_bfloat162*)&kv);
                        dot += f.x * qh[2 * j] + f.y * qh[2 * j + 1];
                    }
                    s = dot * (1.f / 11.313708498984761f);
                }
                float m = s;
#pragma unroll
                for (int o = 16; o > 0; o >>= 1) m = fmaxf(m, __shfl_xor_sync(~0u, m, o));
                if (lane == 0) ared[hB * 8 + (wid & 7)] = m;
                __syncthreads();
                m = ared[hB * 8];
#pragma unroll
                for (int i = 1; i < 8; i++) m = fmaxf(m, ared[hB * 8 + i]);
                float e = (lt < t) ? expf(s - m) : 0.f;
                float su = e;
#pragma unroll
                for (int o = 16; o > 0; o >>= 1) su += __shfl_xor_sync(~0u, su, o);
                __syncthreads();
                if (lane == 0) ared[hB * 8 + (wid & 7)] = su;
                __syncthreads();
                su = 0.f;
#pragma unroll
                for (int i = 0; i < 8; i++) su += ared[hB * 8 + i];
                if (lt < 128) asc[hB * 128 + lt] = (lt < t) ? (e / su) : 0.f;
                __syncthreads();
                {
                    int a = lt & 127, th = lt >> 7;
                    int tlim = (t + 7) & ~7;
                    float c = 0.f;
#pragma unroll 8
                    for (int sx = th; sx < tlim; sx += 2)
                        c += asc[hB * 128 + sx] * g_V[(b * TT + sx) * AA + a];
                    actx[(hB * 2 + th) * 128 + a] = c;
                }
                __syncthreads();
                if (lt < 128)
                    g_ctx[b * AA + lt] = actx[hB * 256 + lt] + actx[hB * 256 + 128 + lt];
            }
            gbar(gid);
        }

        // ---- 4 RK stages ----
        for (int stage = 0; stage < 4; stage++) {
            float acc[3][4];
#pragma unroll
            for (int s = 0; s < 3; s++)
#pragma unroll
                for (int i = 0; i < 4; i++) acc[s][i] = 0.f;

            if (stage == 0) {
                // --- base GEMM: A([x|ctx]) hi at O_Z (stride 100), lo at O_PB ---
                uint32_t* bAhi = (uint32_t*)(smraw + O_Z);
                uint32_t* bAlo = (uint32_t*)(smraw + O_PB);
#pragma unroll
                for (int i = 0; i < 6; i++) {
                    int idx = i * 512 + tid;           // < 3072
                    int m = idx / 96, kq = idx - m * 96;
                    int k0 = kq * 2;
                    float a0, a1;
                    if (kq < 32) {
                        const float* xr = &x_states[((m0 + m) * TT + t) * DD];
                        a0 = xr[k0]; a1 = xr[k0 + 1];
                    } else {
                        const float* cr = &g_ctx[(m0 + m) * AA];
                        a0 = cr[k0 - 64]; a1 = cr[k0 - 63];
                    }
                    float h0v = bfr(a0), h1v = bfr(a1);
                    bAhi[m * 100 + kq] = pack_bf2(h0v, h1v);
                    bAlo[m * 100 + kq] = pack_bf2(a0 - h0v, a1 - h1v);
                }
                __syncthreads();
                {
                    float accb[2][4];
#pragma unroll
                    for (int s = 0; s < 2; s++)
#pragma unroll
                        for (int i = 0; i < 4; i++) accb[s][i] = 0.f;
#pragma unroll
                    for (int ks = 0; ks < 6; ks++) {
                        int kq0 = wbk2 * 48 + ks * 8;
                        uint32_t ahi[4], alo[4];
                        ldsm4(ahi, uZ  + (rowA_bs + kq0) * 4);
                        ldsm4(alo, uPB + (rowA_bs + kq0) * 4);
#pragma unroll
                        for (int s = 0; s < 2; s++) {
                            int nrow = wbn2 * 16 + s * 8 + (lane >> 2);
                            long bix = (long)(bid * 64 + nrow) * 96 + kq0 + qa;
                            uint32_t bhi[2], blo[2];
                            bhi[0] = g_WBaseHi[bix]; bhi[1] = g_WBaseHi[bix + 4];
                            blo[0] = g_WBaseLo[bix]; blo[1] = g_WBaseLo[bix + 4];
                            mma16(accb[s], ahi, bhi);
                            mma16(accb[s], alo, bhi);
                            mma16(accb[s], ahi, blo);
                        }
                    }
                    __syncthreads();
                    float* pb = (float*)(smraw + O_Z);   // baseA hi dead now
#pragma unroll
                    for (int s = 0; s < 2; s++) {
                        int off = wbk2 * 2048 + (wbm2 * 16 + (lane >> 2)) * 64 +
                                  wbn2 * 16 + s * 8 + (lane & 3) * 2;
                        pb[off] = accb[s][0]; pb[off + 1] = accb[s][1];
                        pb[off + 512] = accb[s][2]; pb[off + 513] = accb[s][3];
                    }
                    __syncthreads();
#pragma unroll
                    for (int i = 0; i < 4; i++) {
                        int idx = i * 512 + tid;           // < 2048
                        int m = idx >> 6, n = idx & 63;
                        int col = (n < 32) ? (h0 + n) : (512 + h0 + n - 32);
                        sbase[m][n] = pb[m * 64 + n] + pb[2048 + m * 64 + n] + b_gd[col];
                    }
                }
                __syncthreads();
                // --- A(h): already resident in AsHi/AsLo from KV phase (t>0) ---
                if (t == 0) {
#pragma unroll
                    for (int i = 0; i < 4; i++) {
                        int u4 = i * 512 + tid;
                        int m = u4 >> 6, q4 = u4 & 63;
                        *(uint4*)&AsHi[m * 260 + q4 * 4] = ((const uint4*)&g_hHi[(m0 + m) * 256])[q4];
                        *(uint4*)&AsLo[m * 260 + q4 * 4] = ((const uint4*)&g_hLo[(m0 + m) * 256])[q4];
                    }
                    __syncthreads();
                }
#pragma unroll
                for (int it = 0; it < 8; it++) {
#pragma unroll
                    for (int kb2 = 0; kb2 < 16; kb2 += 8) {
                        int kq0 = kh * 128 + it * 16 + kb2;
                        uint32_t ahi[4], alo[4], bw[2], bl[2];
                        ldsm4(ahi, uA  + (rowA_st + kq0) * 4);
                        ldsm4(alo, uAL + (rowA_st + kq0) * 4);
                        ldsm2(bw, uW + (rowB0 + kq0) * 4);
                        bl[0] = g_WBLo[loN0 + kq0]; bl[1] = g_WBLo[loN0 + kq0 + 4];
                        mma16(acc[0], ahi, bw); mma16(acc[0], alo, bw); mma16(acc[0], ahi, bl);
                        ldsm2(bw, uW + (rowB1 + kq0) * 4);
                        bl[0] = g_WBLo[loN1 + kq0]; bl[1] = g_WBLo[loN1 + kq0 + 4];
                        mma16(acc[1], ahi, bw); mma16(acc[1], alo, bw); mma16(acc[1], ahi, bl);
                        ldsm2(bw, uW + (rowB2 + kq0) * 4);
                        bl[0] = g_WBLo[loN2 + kq0]; bl[1] = g_WBLo[loN2 + kq0 + 4];
                        mma16(acc[2], ahi, bw); mma16(acc[2], alo, bw); mma16(acc[2], ahi, bl);
                    }
                }
                __syncthreads();
            } else {
                const uint32_t* Dg = (stage == 2) ? g_dB : g_dA;
#pragma unroll
                for (int i = 0; i < 4; i++) {
                    int idx = i * 512 + tid;
                    int m = idx >> 6, q4 = idx & 63;
                    *(uint4*)&AsHi[m * 260 + q4 * 4] = ((const uint4*)&Dg[(m0 + m) * 256])[q4];
                }
                __syncthreads();
#pragma unroll
                for (int it = 0; it < 8; it++) {
#pragma unroll
                    for (int kb2 = 0; kb2 < 16; kb2 += 8) {
                        int kq0 = kh * 128 + it * 16 + kb2;
                        uint32_t ahi[4], bw[2];
                        ldsm4(ahi, uA + (rowA_st + kq0) * 4);
                        ldsm2(bw, uW + (rowB0 + kq0) * 4);
                        mma16(acc[0], ahi, bw);
                        ldsm2(bw, uW + (rowB1 + kq0) * 4);
                        mma16(acc[1], ahi, bw);
                        ldsm2(bw, uW + (rowB2 + kq0) * 4);
                        mma16(acc[2], ahi, bw);
                    }
                }
                __syncthreads();
            }

            {
                int rr = wm + (lane >> 2), cc = wn + (lane & 3) * 2;
#pragma unroll
                for (int s = 0; s < 3; s++) {
                    zz[kh * 32 + rr][cc + s * 8]         = acc[s][0];
                    zz[kh * 32 + rr][cc + s * 8 + 1]     = acc[s][1];
                    zz[kh * 32 + rr + 8][cc + s * 8]     = acc[s][2];
                    zz[kh * 32 + rr + 8][cc + s * 8 + 1] = acc[s][3];
                }
            }
            __syncthreads();
            if (stage == 0) {
#pragma unroll
                for (int i = 0; i < 6; i++) {
                    int idx = i * 512 + tid;
                    int bl = idx / 96, c = idx - bl * 96;
                    sz0[bl][c] = zz[bl][c] + zz[32 + bl][c];
                }
                __syncthreads();
            }

#pragma unroll
            for (int p = 0; p < 2; p++) {
                int idx = p * 512 + tid;
                int bl = idx >> 5, hh = idx & 31;
                int b = m0 + bl;
                float zg, zdn, zt;
                if (stage == 0) {
                    zg = sz0[bl][hh]; zdn = sz0[bl][32 + hh]; zt = sz0[bl][64 + hh];
                } else {
                    zg  = sz0[bl][hh]      + zz[bl][hh]      + zz[32 + bl][hh];
                    zdn = sz0[bl][32 + hh] + zz[bl][32 + hh] + zz[32 + bl][32 + hh];
                    zt  = sz0[bl][64 + hh] + zz[bl][64 + hh] + zz[32 + bl][64 + hh];
                }
                float gate = zg + sbase[bl][hh];
                float dyn  = zdn + sbase[bl][32 + hh];
                float tau  = softplusf(zt + sbtau[hh]);
                float hsv  = (stage == 0) ? hreg[p] : (hreg[p] + dd[p]);
                float kd   = (sigmoidf(gate) * tanhf(dyn) - hsv) / (tau + sleak[hh] + 1e-6f);
                float dt   = x_dts[b * TT + t];
                if (stage == 3) {
                    hreg[p] += dt * (rk1[p] + 3.f * rk2[p] + 3.f * rk3[p] + kd) * 0.125f;
                    g_h[b * HH + h0 + hh] = hreg[p];
                    float hi = bfr(hreg[p]);
                    float lo = hreg[p] - hi;
                    float ohi = __shfl_xor_sync(~0u, hi, 1);
                    float olo = __shfl_xor_sync(~0u, lo, 1);
                    if (!(tid & 1)) {
                        g_hHi[b * 256 + ((h0 + hh) >> 1)] = pack_bf2(hi, ohi);
                        g_hLo[b * 256 + ((h0 + hh) >> 1)] = pack_bf2(lo, olo);
                    }
                } else {
                    float dnew;
                    if (stage == 0)      { rk1[p] = kd; dnew = dt * kd * (1.f / 3.f); }
                    else if (stage == 1) { rk2[p] = kd; dnew = dt * (kd - rk1[p] * (1.f / 3.f)); }
                    else                 { rk3[p] = kd; dnew = dt * (rk1[p] - rk2[p] + kd); }
                    dd[p] = dnew;
                    float oth = __shfl_xor_sync(~0u, dnew, 1);
                    if (!(tid & 1)) {
                        uint32_t pk = pack_bf2(dnew, oth);
                        if (stage == 1) g_dB[b * 256 + ((h0 + hh) >> 1)] = pk;
                        else            g_dA[b * 256 + ((h0 + hh) >> 1)] = pk;
                    }
                }
            }
            gbar(gid);
        }
    }

    // ===== final projection =====
    {
        int b = bid * 2 + (tid >> 8);
        int lt = tid & 255;
        if (lt < OO) {
            float acc = b_fc[lt];
#pragma unroll 8
            for (int k = 0; k < HH; k++) acc += g_h[b * HH + k] * W_fc[k * OO + lt];
            out[b * OO + lt] = acc;
        }
    }
}

extern "C" void kernel_launch(void* const* d_in, const int* in_sizes, int n_in,
                              void* d_out, int out_size) {
    const float* x_states = (const float*)d_in[0];
    const float* x_dts    = (const float*)d_in[1];
    const float* Wq = (const float*)d_in[2];  const float* bq = (const float*)d_in[3];
    const float* Wk = (const float*)d_in[4];  const float* bk = (const float*)d_in[5];
    const float* Wv = (const float*)d_in[6];  const float* bv = (const float*)d_in[7];
    const float* W_gd = (const float*)d_in[8]; const float* b_gd = (const float*)d_in[9];
    const float* W_tau = (const float*)d_in[10]; const float* b_tau = (const float*)d_in[11];
    const float* gleak = (const float*)d_in[12]; const float* cm = (const float*)d_in[13];
    const float* W_fc = (const float*)d_in[14]; const float* b_fc = (const float*)d_in[15];
    float* out = (float*)d_out;

    cudaFuncSetAttribute(mega, cudaFuncAttributeMaxDynamicSharedMemorySize, SMEM_BYTES);
    mega<<<NBLK, NTHR, SMEM_BYTES>>>(x_states, x_dts, Wq, bq, Wk, bk, Wv, bv,
                                     W_gd, b_gd, W_tau, b_tau, gleak, cm,
                                     W_fc, b_fc, out);
}